// round 12
// baseline (speedup 1.0000x reference)
#include <cuda_runtime.h>
#include <math.h>

// ---------------- problem constants ----------------
#define BB 4
#define NN 4096
#define N1 1024
#define SCALE 0.17677669529663687f  // 1/sqrt(32)

// ---------------- scratch ----------------
__device__ float g_big [BB*NN*768];   // cols: q1[0,128) q2[128,256) kv2[256,512) lin[512,768)
__device__ float g_lepe[BB*NN*256];
__device__ float g_srwt[1024*256];
__device__ float g_xs  [BB*N1*256];
__device__ float g_kv1 [BB*N1*256];
__device__ float g_att [BB*NN*256];   // x1 in [0,128), x2 in [128,256)
__device__ float g_gacc[BB*N1];
__device__ float g_lmacc[BB*256*16];
__device__ float g_wbig[256*768];
__device__ float g_bbig[768];
__device__ float g_wkv1[256*256];
__device__ float g_wproj[256*256];

// ---------------- helpers ----------------
__device__ __forceinline__ unsigned f2tf(float f) {
    unsigned u;
    asm("cvt.rna.tf32.f32 %0, %1;" : "=r"(u) : "f"(f));
    return u;
}
__device__ __forceinline__ float f2tff(float f) { return __uint_as_float(f2tf(f)); }

__device__ __forceinline__ void mma8(float* d, const unsigned* a, const unsigned* b) {
    asm volatile(
        "mma.sync.aligned.m16n8k8.row.col.f32.tf32.tf32.f32 "
        "{%0,%1,%2,%3}, {%4,%5,%6,%7}, {%8,%9}, {%0,%1,%2,%3};"
        : "+f"(d[0]), "+f"(d[1]), "+f"(d[2]), "+f"(d[3])
        : "r"(a[0]), "r"(a[1]), "r"(a[2]), "r"(a[3]), "r"(b[0]), "r"(b[1]));
}

__device__ __forceinline__ unsigned sptr(const void* p) {
    return (unsigned)__cvta_generic_to_shared(p);
}
#define CPA(dst, src) asm volatile("cp.async.cg.shared.global [%0], [%1], 16;" :: "r"(dst), "l"(src))
#define CPC() asm volatile("cp.async.commit_group;")
#define CPW(n) asm volatile("cp.async.wait_group %0;" :: "n"(n))

// ---------------- fused prep ----------------
__global__ void prep_kernel(const float* __restrict__ q1w, const float* __restrict__ q2w,
                            const float* __restrict__ kv2w, const float* __restrict__ lepew,
                            const float* __restrict__ q1b, const float* __restrict__ q2b,
                            const float* __restrict__ kv2b, const float* __restrict__ lepeb,
                            const float* __restrict__ kv1w, const float* __restrict__ projw,
                            const float* __restrict__ srw,
                            float* __restrict__ wbig, float* __restrict__ bbig,
                            float* __restrict__ wkv1, float* __restrict__ wproj,
                            float* __restrict__ srwt,
                            float* __restrict__ gacc, float* __restrict__ lmacc)
{
    int idx = blockIdx.x * blockDim.x + threadIdx.x;   // 262144
    {
        int o = idx & 255, f = idx >> 8, c = f & 255, q = f >> 8;
        srwt[idx] = f2tff(srw[(o << 10) + (c << 2) + q]);
    }
    if (idx < 196608) {
        int j = idx % 768, k = idx / 768;
        float v;
        if (j < 128)      v = q1w[k * 128 + j];
        else if (j < 256) v = q2w[k * 128 + j - 128];
        else if (j < 512) v = kv2w[k * 256 + j - 256];
        else              v = lepew[k * 256 + j - 512];
        wbig[idx] = f2tff(v);
        if (k == 0) {
            float bv;
            if (j < 128)      bv = q1b[j];
            else if (j < 256) bv = q2b[j - 128];
            else if (j < 512) bv = kv2b[j - 256];
            else              bv = lepeb[j - 512];
            bbig[j] = bv;
        }
    }
    if (idx < 65536) {
        wkv1[idx]  = f2tff(kv1w[idx]);
        wproj[idx] = f2tff(projw[idx]);
    }
    if (idx < 16384) lmacc[idx] = 0.f;
    if (idx < 4096)  gacc[idx]  = 0.f;
}

// ---------------- pipelined tf32 GEMM core ----------------
template<int FUSE, int XCOL>
__device__ __forceinline__ void gemm_core(
    const float* __restrict__ A, const float* __restrict__ A2,
    const float* __restrict__ Bw, const float* __restrict__ bias,
    float* __restrict__ C, int K, int Nn, float oscale, int oround,
    int bx, int by, float* smx)
{
    float* As = smx;                   // [2][128*36]
    float* Bs = smx + 2 * 4608;        // [2][32*136]
    float* biass = smx + 2 * 4608 + 2 * 4352;
    const int tid = threadIdx.x, warp = tid >> 5, lane = tid & 31;
    const int m0 = by * 128, n0 = bx * 128;
    const int wm = (warp & 1) * 64, wn = (warp >> 1) * 32;
    if (tid < 128) biass[tid] = bias[n0 + tid];

    float acc[4][4][4];
#pragma unroll
    for (int i = 0; i < 4; ++i)
#pragma unroll
        for (int j = 0; j < 4; ++j)
#pragma unroll
            for (int k = 0; k < 4; ++k) acc[i][j][k] = 0.f;

    const int am = tid >> 1, akb = (tid & 1) * 16;
    const int bk = tid >> 3, bnb = (tid & 7) * 16;
    const int row = m0 + am;
    const int xb = row >> 10, xm = row & 1023;
    const int ii2 = (xm >> 5) << 1, jj2 = (xm & 31) << 1;
    const int basepix = xb << 12;

    const float* Ap  = A + (size_t)row * K + akb;
    const float* A2p = FUSE ? (A2 + (size_t)row * K + akb) : (const float*)0;
    const float* Bp  = Bw + (size_t)bk * Nn + n0 + bnb;
    const unsigned BsW = sptr(Bs) + (bk * 136 + bnb) * 4;

    float4 ar[4], ar2[4];
#pragma unroll
    for (int i = 0; i < 4; ++i) {
        if (XCOL) {
            int k = akb + i * 4, f = k >> 8, cc = k & 255;
            int n = ((ii2 + (f >> 1)) << 6) + jj2 + (f & 1);
            ar[i] = *(const float4*)&A[(size_t)(basepix + n) * 256 + cc];
        } else {
            ar[i] = *(const float4*)(Ap + i * 4);
        }
    }
    if (FUSE) {
#pragma unroll
        for (int i = 0; i < 4; ++i) ar2[i] = *(const float4*)(A2p + i * 4);
    }
#pragma unroll
    for (int i = 0; i < 4; ++i) CPA(BsW + i * 16, Bp + i * 4);
    CPC();

    const int nc = K >> 5;
    for (int c = 0; c < nc; ++c) {
        const int buf = c & 1;
        CPW(0);
        {
            float* dst = As + buf * 4608 + am * 36 + akb;
#pragma unroll
            for (int i = 0; i < 4; ++i) {
                float4 v = ar[i];
                if (FUSE) { float4 w = ar2[i]; v.x += w.x; v.y += w.y; v.z += w.z; v.w += w.w; }
                dst[i * 4 + 0] = f2tff(v.x); dst[i * 4 + 1] = f2tff(v.y);
                dst[i * 4 + 2] = f2tff(v.z); dst[i * 4 + 3] = f2tff(v.w);
            }
        }
        __syncthreads();
        if (c + 1 < nc) {
            const float* bp = Bp + (size_t)(c + 1) * 32 * Nn;
            unsigned w = BsW + (buf ^ 1) * (4352 * 4);
#pragma unroll
            for (int i = 0; i < 4; ++i) CPA(w + i * 16, bp + i * 4);
            CPC();
#pragma unroll
            for (int i = 0; i < 4; ++i) {
                if (XCOL) {
                    int k = (c + 1) * 32 + akb + i * 4, f = k >> 8, cc = k & 255;
                    int n = ((ii2 + (f >> 1)) << 6) + jj2 + (f & 1);
                    ar[i] = *(const float4*)&A[(size_t)(basepix + n) * 256 + cc];
                } else {
                    ar[i] = *(const float4*)(Ap + (c + 1) * 32 + i * 4);
                }
            }
            if (FUSE) {
                const float* a2p = A2p + (c + 1) * 32;
#pragma unroll
                for (int i = 0; i < 4; ++i) ar2[i] = *(const float4*)(a2p + i * 4);
            }
        }
        const float* Ab = As + buf * 4608;
        const float* Bb = Bs + buf * 4352;
#pragma unroll
        for (int ks = 0; ks < 4; ++ks) {
            unsigned a[4][4], bfr[4][2];
#pragma unroll
            for (int mt = 0; mt < 4; ++mt) {
                int r = wm + mt * 16 + (lane >> 2), cc = ks * 8 + (lane & 3);
                a[mt][0] = __float_as_uint(Ab[r * 36 + cc]);
                a[mt][1] = __float_as_uint(Ab[(r + 8) * 36 + cc]);
                a[mt][2] = __float_as_uint(Ab[r * 36 + cc + 4]);
                a[mt][3] = __float_as_uint(Ab[(r + 8) * 36 + cc + 4]);
            }
#pragma unroll
            for (int nt = 0; nt < 4; ++nt) {
                int n = wn + nt * 8 + (lane >> 2), kr = ks * 8 + (lane & 3);
                bfr[nt][0] = __float_as_uint(Bb[kr * 136 + n]);
                bfr[nt][1] = __float_as_uint(Bb[(kr + 4) * 136 + n]);
            }
#pragma unroll
            for (int mt = 0; mt < 4; ++mt)
#pragma unroll
                for (int nt = 0; nt < 4; ++nt) mma8(acc[mt][nt], a[mt], bfr[nt]);
        }
    }

#pragma unroll
    for (int mt = 0; mt < 4; ++mt) {
        int r = m0 + wm + mt * 16 + (lane >> 2);
#pragma unroll
        for (int nt = 0; nt < 4; ++nt) {
            int cc = wn + nt * 8 + (lane & 3) * 2;
            float o0 = (acc[mt][nt][0] + biass[cc]) * oscale;
            float o1 = (acc[mt][nt][1] + biass[cc + 1]) * oscale;
            float o2 = (acc[mt][nt][2] + biass[cc]) * oscale;
            float o3 = (acc[mt][nt][3] + biass[cc + 1]) * oscale;
            if (oround) { o0 = f2tff(o0); o1 = f2tff(o1); o2 = f2tff(o2); o3 = f2tff(o3); }
            *(float2*)&C[(size_t)r * Nn + n0 + cc] = make_float2(o0, o1);
            *(float2*)&C[(size_t)(r + 8) * Nn + n0 + cc] = make_float2(o2, o3);
        }
    }
}

// ---------------- mega1: big linear GEMM || sr conv GEMM (im2col fused) ----------------
__global__ __launch_bounds__(256, 2) void mega1_kernel(
    const float* __restrict__ x,
    const float* __restrict__ wbig, const float* __restrict__ bbig, float* __restrict__ big,
    const float* __restrict__ srwt, const float* __restrict__ srb, float* __restrict__ xs)
{
    extern __shared__ float smx[];
    if (blockIdx.x < 6) {
        gemm_core<0, 0>(x, nullptr, wbig, bbig, big, 256, 768, 1.f, 1,
                        blockIdx.x, blockIdx.y, smx);
    } else if (blockIdx.y < 32) {
        gemm_core<0, 1>(x, nullptr, srwt, srb, xs, 1024, 256, 1.f, 0,
                        blockIdx.x - 6, blockIdx.y, smx);
    }
}

// ---------------- kv1ln: fused LayerNorm+GELU+GEMM ----------------
// grid (2, 64): 64-row tiles, N-tile 128. smem: xt[64][260] | Bs[2][4352] | biass[128]
__global__ __launch_bounds__(256, 2) void kv1ln_kernel(
    const float* __restrict__ xs, const float* __restrict__ wkv1,
    const float* __restrict__ kv1b, const float* __restrict__ normw,
    const float* __restrict__ normb, float* __restrict__ kv1)
{
    extern __shared__ float smx[];
    float* xt = smx;                       // 16640
    float* Bs = smx + 16640;               // 8704
    float* biass = smx + 16640 + 8704;     // 128
    const int tid = threadIdx.x, warp = tid >> 5, lane = tid & 31;
    const int m0 = blockIdx.y * 64, n0 = blockIdx.x * 128;
    if (tid < 128) biass[tid] = kv1b[n0 + tid];

    // stage 64x256 xs tile
    const int r = tid >> 2, cq = (tid & 3) * 64;
    {
        const float* src = xs + (size_t)(m0 + r) * 256 + cq;
#pragma unroll
        for (int i = 0; i < 16; ++i)
            *(float4*)&xt[r * 260 + cq + i * 4] = *(const float4*)(src + i * 4);
    }
    __syncthreads();

    // LN + GELU in place (tf32-rounded result)
    {
        float s = 0.f, s2 = 0.f;
#pragma unroll
        for (int i = 0; i < 64; ++i) { float v = xt[r * 260 + cq + i]; s += v; s2 += v * v; }
        s  += __shfl_xor_sync(0xffffffffu, s, 1);  s  += __shfl_xor_sync(0xffffffffu, s, 2);
        s2 += __shfl_xor_sync(0xffffffffu, s2, 1); s2 += __shfl_xor_sync(0xffffffffu, s2, 2);
        float mean = s * (1.f / 256.f);
        float var = s2 * (1.f / 256.f) - mean * mean;
        float inv = rsqrtf(var + 1e-5f);
#pragma unroll 8
        for (int i = 0; i < 64; ++i) {
            int c = cq + i;
            float y = (xt[r * 260 + c] - mean) * inv * normw[c] + normb[c];
            xt[r * 260 + c] = f2tff(0.5f * y * (1.0f + erff(y * 0.70710678118654752f)));
        }
    }
    __syncthreads();

    // GEMM: warp tile 32x32 (2 mt x 4 nt)
    const int wm = (warp & 1) * 32, wn = (warp >> 1) * 32;
    float acc[2][4][4];
#pragma unroll
    for (int i = 0; i < 2; ++i)
#pragma unroll
        for (int j = 0; j < 4; ++j)
#pragma unroll
            for (int k = 0; k < 4; ++k) acc[i][j][k] = 0.f;

    const int bk = tid >> 3, bnb = (tid & 7) * 16;
    const float* Bp = wkv1 + (size_t)bk * 256 + n0 + bnb;
    const unsigned BsW = sptr(Bs) + (bk * 136 + bnb) * 4;
#pragma unroll
    for (int i = 0; i < 4; ++i) CPA(BsW + i * 16, Bp + i * 4);
    CPC();

    for (int c = 0; c < 8; ++c) {
        const int buf = c & 1;
        CPW(0);
        __syncthreads();
        if (c < 7) {
            const float* bp = Bp + (size_t)(c + 1) * 32 * 256;
            unsigned w = BsW + (buf ^ 1) * (4352 * 4);
#pragma unroll
            for (int i = 0; i < 4; ++i) CPA(w + i * 16, bp + i * 4);
            CPC();
        }
        const float* Bb = Bs + buf * 4352;
#pragma unroll
        for (int ks = 0; ks < 4; ++ks) {
            unsigned a[2][4], bfr[4][2];
#pragma unroll
            for (int mt = 0; mt < 2; ++mt) {
                int rr = wm + mt * 16 + (lane >> 2), cc = c * 32 + ks * 8 + (lane & 3);
                a[mt][0] = __float_as_uint(xt[rr * 260 + cc]);
                a[mt][1] = __float_as_uint(xt[(rr + 8) * 260 + cc]);
                a[mt][2] = __float_as_uint(xt[rr * 260 + cc + 4]);
                a[mt][3] = __float_as_uint(xt[(rr + 8) * 260 + cc + 4]);
            }
#pragma unroll
            for (int nt = 0; nt < 4; ++nt) {
                int n = wn + nt * 8 + (lane >> 2), kr = ks * 8 + (lane & 3);
                bfr[nt][0] = __float_as_uint(Bb[kr * 136 + n]);
                bfr[nt][1] = __float_as_uint(Bb[(kr + 4) * 136 + n]);
            }
#pragma unroll
            for (int mt = 0; mt < 2; ++mt)
#pragma unroll
                for (int nt = 0; nt < 4; ++nt) mma8(acc[mt][nt], a[mt], bfr[nt]);
        }
        __syncthreads();
    }

#pragma unroll
    for (int mt = 0; mt < 2; ++mt) {
        int rr = m0 + wm + mt * 16 + (lane >> 2);
#pragma unroll
        for (int nt = 0; nt < 4; ++nt) {
            int cc = wn + nt * 8 + (lane & 3) * 2;
            float o0 = f2tff(acc[mt][nt][0] + biass[cc]);
            float o1 = f2tff(acc[mt][nt][1] + biass[cc + 1]);
            float o2 = f2tff(acc[mt][nt][2] + biass[cc]);
            float o3 = f2tff(acc[mt][nt][3] + biass[cc + 1]);
            *(float2*)&kv1[(size_t)rr * 256 + n0 + cc] = make_float2(o0, o1);
            *(float2*)&kv1[(size_t)(rr + 8) * 256 + n0 + cc] = make_float2(o2, o3);
        }
    }
}

// ---------------- mega3: two-pass attn1 || attn2 || dwconv ----------------
// attn1 smem (floats): qs 0 | kv 1152 | P 10368 | mz 14592 | mzf 16640 | gcol 16704 | op 17728
#define M3_SMEM_FLOATS 22080

__global__ __launch_bounds__(256, 2) void mega3_kernel(
    const float* __restrict__ big, const float* __restrict__ kv1,
    float* __restrict__ att_out, float* __restrict__ gacc, float* __restrict__ lmacc,
    const float* __restrict__ cw, const float* __restrict__ cb, float* __restrict__ lepe)
{
    extern __shared__ float sm[];
    const int bid = blockIdx.x;
    const int tid = threadIdx.x;

    if (bid < 2048) {
        // ================= attn1: 32 queries, two-pass exact softmax =================
        float* qs   = sm;            // 32x36
        float* kv   = sm + 1152;     // 2 x 4608
        float* P    = sm + 10368;    // 32x132
        float* mz   = sm + 14592;    // [8ch][4wk][32] float2
        float* mzf  = sm + 16640;    // 32 float2
        float* gcol = sm + 16704;    // 1024
        float* op   = sm + 17728;    // 8x544

        const int warp = tid >> 5, lane = tid & 31;
        const int bh = bid >> 7, b = bh >> 2, h = bh & 3;
        const int q0 = (bid & 127) * 32;
        const int wq = warp & 1, wk = warp >> 1, wr = warp >> 1;

        for (int i = tid; i < 1024; i += 256) gcol[i] = 0.f;
        {
            int q = tid >> 3, d4 = (tid & 7) * 4;
            float4 v = *(const float4*)&big[(size_t)(b * 4096 + q0 + q) * 768 + h * 32 + d4];
            float* p = &qs[q * 36 + d4];
            p[0] = v.x; p[1] = v.y; p[2] = v.z; p[3] = v.w;
        }
        const int jj = tid >> 1, db = (tid & 1) * 16;
        const size_t kbase = (size_t)(b * 1024) * 256 + h * 32;
        const size_t vbase = kbase + 128;
        const unsigned kvW = sptr(kv) + (jj * 36 + db) * 4;
        {
            const float* src = kv1 + kbase + (size_t)jj * 256 + db;
#pragma unroll
            for (int i = 0; i < 4; ++i) CPA(kvW + i * 16, src + i * 4);
            CPC();
        }
        __syncthreads();

        unsigned qa[4][4];
#pragma unroll
        for (int ks = 0; ks < 4; ++ks) {
            int r = wq * 16 + (lane >> 2), cc = ks * 8 + (lane & 3);
            qa[ks][0] = __float_as_uint(qs[r * 36 + cc]);
            qa[ks][1] = __float_as_uint(qs[(r + 8) * 36 + cc]);
            qa[ks][2] = __float_as_uint(qs[r * 36 + cc + 4]);
            qa[ks][3] = __float_as_uint(qs[(r + 8) * 36 + cc + 4]);
        }

        // ---- pass 1: per-chunk per-segment (max, expsum) ----
        for (int ch = 0; ch < 8; ++ch) {
            CPW(0);
            __syncthreads();
            if (ch < 7) {
                const float* src = kv1 + kbase + (size_t)((ch + 1) * 128 + jj) * 256 + db;
                unsigned w = kvW + (((ch & 1) ^ 1)) * (4608 * 4);
#pragma unroll
                for (int i = 0; i < 4; ++i) CPA(w + i * 16, src + i * 4);
                CPC();
            }
            const float* kb = kv + (ch & 1) * 4608;
            float c4[4][4];
#pragma unroll
            for (int nt = 0; nt < 4; ++nt)
#pragma unroll
                for (int k = 0; k < 4; ++k) c4[nt][k] = 0.f;
#pragma unroll
            for (int ks = 0; ks < 4; ++ks) {
#pragma unroll
                for (int nt = 0; nt < 4; ++nt) {
                    int n = wk * 32 + nt * 8 + (lane >> 2), dr = ks * 8 + (lane & 3);
                    unsigned bb2[2] = { __float_as_uint(kb[n * 36 + dr]),
                                        __float_as_uint(kb[n * 36 + dr + 4]) };
                    mma8(c4[nt], qa[ks], bb2);
                }
            }
#pragma unroll
            for (int nt = 0; nt < 4; ++nt)
#pragma unroll
                for (int k = 0; k < 4; ++k) c4[nt][k] *= SCALE;
#pragma unroll
            for (int rr = 0; rr < 2; ++rr) {
                float m = -1e30f;
#pragma unroll
                for (int nt = 0; nt < 4; ++nt)
                    m = fmaxf(m, fmaxf(c4[nt][2 * rr], c4[nt][2 * rr + 1]));
                m = fmaxf(m, __shfl_xor_sync(0xffffffffu, m, 1));
                m = fmaxf(m, __shfl_xor_sync(0xffffffffu, m, 2));
                float z = 0.f;
#pragma unroll
                for (int nt = 0; nt < 4; ++nt)
                    z += __expf(c4[nt][2 * rr] - m) + __expf(c4[nt][2 * rr + 1] - m);
                z += __shfl_xor_sync(0xffffffffu, z, 1);
                z += __shfl_xor_sync(0xffffffffu, z, 2);
                if ((lane & 3) == 0) {
                    int row = wq * 16 + (lane >> 2) + rr * 8;
                    *(float2*)&mz[((ch * 4 + wk) * 32 + row) * 2] = make_float2(m, z);
                }
            }
        }
        __syncthreads();

        // merge 32 (m,z) pairs per row
        if (tid < 32) {
            float M = -1e30f, Z = 0.f;
#pragma unroll 4
            for (int i = 0; i < 32; ++i) {
                float2 t = *(float2*)&mz[(i * 32 + tid) * 2];
                float nm = fmaxf(M, t.x);
                Z = Z * __expf(M - nm) + t.y * __expf(t.x - nm);
                M = nm;
            }
            *(float2*)&mzf[tid * 2] = make_float2(M, 1.f / Z);
        }
        __syncthreads();

        const float2 mzr0 = *(float2*)&mzf[(wq * 16 + (lane >> 2)) * 2];
        const float2 mzr1 = *(float2*)&mzf[(wq * 16 + (lane >> 2) + 8) * 2];

        // ---- pass 2: recompute QK, normalize, PV + gcol ----
        {
            const float* srcK = kv1 + kbase + (size_t)jj * 256 + db;
#pragma unroll
            for (int i = 0; i < 4; ++i) CPA(kvW + i * 16, srcK + i * 4);
            CPC();
            const float* srcV = kv1 + vbase + (size_t)jj * 256 + db;
            unsigned w = kvW + 4608 * 4;
#pragma unroll
            for (int i = 0; i < 4; ++i) CPA(w + i * 16, srcV + i * 4);
            CPC();
        }
        float o4[4][4];
#pragma unroll
        for (int nt = 0; nt < 4; ++nt)
#pragma unroll
            for (int k = 0; k < 4; ++k) o4[nt][k] = 0.f;

        for (int ch = 0; ch < 8; ++ch) {
            CPW(1);
            __syncthreads();
            // QK from buf0
            {
                const float* kb = kv;
                float c4[4][4];
#pragma unroll
                for (int nt = 0; nt < 4; ++nt)
#pragma unroll
                    for (int k = 0; k < 4; ++k) c4[nt][k] = 0.f;
#pragma unroll
                for (int ks = 0; ks < 4; ++ks) {
#pragma unroll
                    for (int nt = 0; nt < 4; ++nt) {
                        int n = wk * 32 + nt * 8 + (lane >> 2), dr = ks * 8 + (lane & 3);
                        unsigned bb2[2] = { __float_as_uint(kb[n * 36 + dr]),
                                            __float_as_uint(kb[n * 36 + dr + 4]) };
                        mma8(c4[nt], qa[ks], bb2);
                    }
                }
                int r = wq * 16 + (lane >> 2);
#pragma unroll
                for (int nt = 0; nt < 4; ++nt) {
                    int col = wk * 32 + nt * 8 + (lane & 3) * 2;
                    float p0 = __expf(c4[nt][0] * SCALE - mzr0.x) * mzr0.y;
                    float p1 = __expf(c4[nt][1] * SCALE - mzr0.x) * mzr0.y;
                    float p2 = __expf(c4[nt][2] * SCALE - mzr1.x) * mzr1.y;
                    float p3 = __expf(c4[nt][3] * SCALE - mzr1.x) * mzr1.y;
                    *(float2*)&P[r * 132 + col] = make_float2(f2tff(p0), f2tff(p1));
                    *(float2*)&P[(r + 8) * 132 + col] = make_float2(f2tff(p2), f2tff(p3));
                }
            }
            __syncthreads();
            if (ch < 7) {
                const float* src = kv1 + kbase + (size_t)((ch + 1) * 128 + jj) * 256 + db;
#pragma unroll
                for (int i = 0; i < 4; ++i) CPA(kvW + i * 16, src + i * 4);
                CPC();
            }
            if (tid < 128) {
                float ssum = 0.f;
#pragma unroll 8
                for (int r = 0; r < 32; ++r) ssum += P[r * 132 + tid];
                gcol[ch * 128 + tid] += ssum;
            }
            CPW(1);
            __syncthreads();
            // PV from buf1
            {
                const float* vb = kv + 4608;
#pragma unroll
                for (int ks = 0; ks < 4; ++ks) {
                    int r = wq * 16 + (lane >> 2), c = wr * 32 + ks * 8 + (lane & 3);
                    unsigned a[4] = { __float_as_uint(P[r * 132 + c]),
                                      __float_as_uint(P[(r + 8) * 132 + c]),
                                      __float_as_uint(P[r * 132 + c + 4]),
                                      __float_as_uint(P[(r + 8) * 132 + c + 4]) };
                    int jl = wr * 32 + ks * 8 + (lane & 3);
#pragma unroll
                    for (int nt = 0; nt < 4; ++nt) {
                        int d = nt * 8 + (lane >> 2);
                        unsigned bb2[2] = { __float_as_uint(vb[jl * 36 + d]),
                                            __float_as_uint(vb[(jl + 4) * 36 + d]) };
                        mma8(o4[nt], a, bb2);
                    }
                }
            }
            __syncthreads();
            if (ch < 7) {
                const float* src = kv1 + vbase + (size_t)((ch + 1) * 128 + jj) * 256 + db;
                unsigned w = kvW + 4608 * 4;
#pragma unroll
                for (int i = 0; i < 4; ++i) CPA(w + i * 16, src + i * 4);
                CPC();
            }
        }

        // reduce partial O over 4 key-split warps, write out, flush gcol
#pragma unroll
        for (int nt = 0; nt < 4; ++nt) {
            int rr = lane >> 2, col = nt * 8 + (lane & 3) * 2;
            *(float2*)&op[warp * 544 + rr * 34 + col] = make_float2(o4[nt][0], o4[nt][1]);
            *(float2*)&op[warp * 544 + (rr + 8) * 34 + col] = make_float2(o4[nt][2], o4[nt][3]);
        }
        __syncthreads();
#pragma unroll
        for (int i = 0; i < 4; ++i) {
            int idx = tid + 256 * i;
            int q = idx >> 5, d = idx & 31;
            int wq2 = q >> 4, ql = q & 15;
            float s = op[(0 + wq2) * 544 + ql * 34 + d] + op[(2 + wq2) * 544 + ql * 34 + d]
                    + op[(4 + wq2) * 544 + ql * 34 + d] + op[(6 + wq2) * 544 + ql * 34 + d];
            att_out[(size_t)(b * 4096 + q0 + q) * 256 + h * 32 + d] = s;
        }
        for (int i = tid; i < 1024; i += 256) atomicAdd(&gacc[(b << 10) + i], gcol[i]);
    } else if (bid < 2560) {
        // ================= attn2: 4x4 window attention =================
        if (tid >= 128) return;
        float* ks = sm;
        float* vs = sm + 8 * 528;
        float* ps = sm + 16 * 528;
        const int g = tid >> 4, t = tid & 15;
        const int w = ((bid - 2048) << 3) + g;
        const int b = w >> 10, h = (w >> 8) & 3, win = w & 255;
        const int wy = win >> 4, wx = win & 15;
        const int n = ((wy << 2) + (t >> 2)) * 64 + (wx << 2) + (t & 3);

        const float* row = &big[((size_t)(b * 4096 + n)) * 768];
        float qr[32];
#pragma unroll
        for (int dd = 0; dd < 32; ++dd) {
            ks[(g * 16 + t) * 33 + dd] = row[256 + h * 32 + dd];
            vs[(g * 16 + t) * 33 + dd] = row[384 + h * 32 + dd];
            qr[dd] = row[128 + h * 32 + dd];
        }
        __syncwarp(0xffffffffu);

        float s[16];
        float mx = -1e30f;
#pragma unroll
        for (int m = 0; m < 16; ++m) {
            float a = 0.f;
#pragma unroll
            for (int dd = 0; dd < 32; ++dd) a += qr[dd] * ks[(g * 16 + m) * 33 + dd];
            s[m] = a * SCALE;
            mx = fmaxf(mx, s[m]);
        }
        float sum = 0.f;
#pragma unroll
        for (int m = 0; m < 16; ++m) { s[m] = __expf(s[m] - mx); sum += s[m]; }
        float inv = 1.f / sum;

        float o[32];
#pragma unroll
        for (int dd = 0; dd < 32; ++dd) o[dd] = 0.f;
#pragma unroll
        for (int m = 0; m < 16; ++m) {
            float p = s[m] * inv;
            ps[(g * 16 + t) * 17 + m] = p;
#pragma unroll
            for (int dd = 0; dd < 32; ++dd) o[dd] += p * vs[(g * 16 + m) * 33 + dd];
        }
        float* orow = &att_out[((size_t)(b * 4096 + n)) * 256 + 128 + h * 32];
#pragma unroll
        for (int dd = 0; dd < 32; ++dd) orow[dd] = o[dd];
        __syncwarp(0xffffffffu);

        float cs = 0.f;
#pragma unroll
        for (int qq = 0; qq < 16; ++qq) cs += ps[(g * 16 + qq) * 17 + t];
        atomicAdd(&lmacc[((b << 8) + win) * 16 + t], cs);
    } else {
        // ================= dwconv: lepe depthwise 3x3 =================
        int idx = (bid - 2560) * 256 + tid;  // BB*NN*64
        int c4 = idx & 63;
        int n = (idx >> 6) & 4095;
        int b = idx >> 18;
        int y = n >> 6, x = n & 63;
        int c = c4 << 2;
        float4 acc = make_float4(cb[c], cb[c + 1], cb[c + 2], cb[c + 3]);
#pragma unroll
        for (int dy = 0; dy < 3; ++dy) {
            int yy = y + dy - 1;
            if ((unsigned)yy >= 64u) continue;
#pragma unroll
            for (int dx = 0; dx < 3; ++dx) {
                int xx = x + dx - 1;
                if ((unsigned)xx >= 64u) continue;
                float4 v = *(const float4*)&big[((size_t)((b << 12) + (yy << 6) + xx)) * 768 + 512 + c];
                int wi = dy * 3 + dx;
                acc.x += v.x * cw[(c + 0) * 9 + wi];
                acc.y += v.y * cw[(c + 1) * 9 + wi];
                acc.z += v.z * cw[(c + 2) * 9 + wi];
                acc.w += v.w * cw[(c + 3) * 9 + wi];
            }
        }
        *(float4*)&lepe[((size_t)((b << 12) + n)) * 256 + c] = acc;
    }
}

// ---------------- projmask: final projection GEMM || mask assembly ----------------
__global__ __launch_bounds__(256, 2) void projmask_kernel(
    const float* __restrict__ att, const float* __restrict__ lepe,
    const float* __restrict__ wproj, const float* __restrict__ projb,
    float* __restrict__ out,
    const float* __restrict__ gacc, const float* __restrict__ lmacc)
{
    extern __shared__ float smx[];
    if (blockIdx.x < 2) {
        gemm_core<1, 0>(att, lepe, wproj, projb, out, 256, 256, 2.f, 0,
                        blockIdx.x, blockIdx.y, smx);
    } else if (blockIdx.y < 64) {
        int idx = blockIdx.y * 256 + threadIdx.x;
        int b = idx >> 12, n = idx & 4095;
        int y = n >> 6, x = n & 63;
        float gv = gacc[(b << 10) + ((y >> 1) << 5) + (x >> 1)] * (1.f / 16384.f);
        float lv = lmacc[((b << 8) + ((y >> 2) << 4) + (x >> 2)) * 16 + ((y & 3) << 2) + (x & 3)] * (1.f / 64.f);
        float m = gv + lv;
        out[4194304 + (b << 12) + (y << 6) + x] = m;
        out[4210688 + (b << 12) + (x << 6) + y] = m;
    }
}

// ---------------- host launcher ----------------
extern "C" void kernel_launch(void* const* d_in, const int* in_sizes, int n_in,
                              void* d_out, int out_size)
{
    const float* x        = (const float*)d_in[0];
    const float* q1_w     = (const float*)d_in[1];
    const float* q1_b     = (const float*)d_in[2];
    const float* kv1_w    = (const float*)d_in[3];
    const float* kv1_b    = (const float*)d_in[4];
    const float* q2_w     = (const float*)d_in[5];
    const float* q2_b     = (const float*)d_in[6];
    const float* kv2_w    = (const float*)d_in[7];
    const float* kv2_b    = (const float*)d_in[8];
    const float* lepe_w   = (const float*)d_in[9];
    const float* lepe_b   = (const float*)d_in[10];
    const float* lepe_cw  = (const float*)d_in[11];
    const float* lepe_cb  = (const float*)d_in[12];
    const float* sr_w     = (const float*)d_in[13];
    const float* sr_b     = (const float*)d_in[14];
    const float* norm_w   = (const float*)d_in[15];
    const float* norm_b   = (const float*)d_in[16];
    const float* proj_w   = (const float*)d_in[17];
    const float* proj_b   = (const float*)d_in[18];
    float* out = (float*)d_out;

    float *p_big, *p_lepe, *p_srwt, *p_xs, *p_kv1, *p_att, *p_g, *p_lm;
    float *p_wbig, *p_bbig, *p_wkv1, *p_wproj;
    cudaGetSymbolAddress((void**)&p_big,   g_big);
    cudaGetSymbolAddress((void**)&p_lepe,  g_lepe);
    cudaGetSymbolAddress((void**)&p_srwt,  g_srwt);
    cudaGetSymbolAddress((void**)&p_xs,    g_xs);
    cudaGetSymbolAddress((void**)&p_kv1,   g_kv1);
    cudaGetSymbolAddress((void**)&p_att,   g_att);
    cudaGetSymbolAddress((void**)&p_g,     g_gacc);
    cudaGetSymbolAddress((void**)&p_lm,    g_lmacc);
    cudaGetSymbolAddress((void**)&p_wbig,  g_wbig);
    cudaGetSymbolAddress((void**)&p_bbig,  g_bbig);
    cudaGetSymbolAddress((void**)&p_wkv1,  g_wkv1);
    cudaGetSymbolAddress((void**)&p_wproj, g_wproj);

    const int gsm = (2 * 4608 + 2 * 4352 + 128) * (int)sizeof(float);  // 72192 B
    cudaFuncSetAttribute(mega1_kernel,    cudaFuncAttributeMaxDynamicSharedMemorySize, gsm);
    cudaFuncSetAttribute(projmask_kernel, cudaFuncAttributeMaxDynamicSharedMemorySize, gsm);
    const int ksm = (16640 + 8704 + 128) * (int)sizeof(float);         // 101888 B
    cudaFuncSetAttribute(kv1ln_kernel,    cudaFuncAttributeMaxDynamicSharedMemorySize, ksm);
    const int m3sm = M3_SMEM_FLOATS * (int)sizeof(float);              // 88320 B
    cudaFuncSetAttribute(mega3_kernel,    cudaFuncAttributeMaxDynamicSharedMemorySize, m3sm);

    // 1. fused prep
    prep_kernel<<<1024, 256>>>(q1_w, q2_w, kv2_w, lepe_w, q1_b, q2_b, kv2_b, lepe_b,
                               kv1_w, proj_w, sr_w,
                               p_wbig, p_bbig, p_wkv1, p_wproj, p_srwt, p_g, p_lm);

    // 2. big linear GEMM || sr conv GEMM
    mega1_kernel<<<dim3(8, 128), 256, gsm>>>(x, p_wbig, p_bbig, p_big, p_srwt, sr_b, p_xs);

    // 3. fused LN+GELU+kv1 GEMM
    kv1ln_kernel<<<dim3(2, 64), 256, ksm>>>(p_xs, p_wkv1, kv1_b, norm_w, norm_b, p_kv1);

    // 4. two-pass attn1 || attn2 || dwconv
    mega3_kernel<<<6656, 256, m3sm>>>(p_big, p_kv1, p_att, p_g, p_lm,
                                      lepe_cw, lepe_cb, p_lepe);

    // 5. projection GEMM || mask assembly
    projmask_kernel<<<dim3(3, 128), 256, gsm>>>(p_att, p_lepe, p_wproj, proj_b, out, p_g, p_lm);
}

// round 14
// speedup vs baseline: 1.1498x; 1.1498x over previous
#include <cuda_runtime.h>
#include <math.h>

// ---------------- problem constants ----------------
#define BB 4
#define NN 4096
#define N1 1024
#define SCALE 0.17677669529663687f  // 1/sqrt(32)

// ---------------- scratch ----------------
__device__ float g_big [BB*NN*768];   // cols: q1[0,128) q2[128,256) kv2[256,512) lin[512,768)
__device__ float g_lepe[BB*NN*256];
__device__ float g_srwt[1024*256];
__device__ float g_xs  [BB*N1*256];
__device__ float g_kv1 [BB*N1*256];
__device__ float g_att [BB*NN*256];   // x1 in [0,128), x2 in [128,256)
__device__ float g_gacc[BB*N1];
__device__ float g_lmacc[BB*256*16];
__device__ float g_wbig[256*768];
__device__ float g_bbig[768];
__device__ float g_wkv1[256*256];
__device__ float g_wproj[256*256];

// ---------------- helpers ----------------
__device__ __forceinline__ unsigned f2tf(float f) {
    unsigned u;
    asm("cvt.rna.tf32.f32 %0, %1;" : "=r"(u) : "f"(f));
    return u;
}
__device__ __forceinline__ float f2tff(float f) { return __uint_as_float(f2tf(f)); }

__device__ __forceinline__ void mma8(float* d, const unsigned* a, const unsigned* b) {
    asm volatile(
        "mma.sync.aligned.m16n8k8.row.col.f32.tf32.tf32.f32 "
        "{%0,%1,%2,%3}, {%4,%5,%6,%7}, {%8,%9}, {%0,%1,%2,%3};"
        : "+f"(d[0]), "+f"(d[1]), "+f"(d[2]), "+f"(d[3])
        : "r"(a[0]), "r"(a[1]), "r"(a[2]), "r"(a[3]), "r"(b[0]), "r"(b[1]));
}

__device__ __forceinline__ unsigned sptr(const void* p) {
    return (unsigned)__cvta_generic_to_shared(p);
}
#define CPA(dst, src) asm volatile("cp.async.cg.shared.global [%0], [%1], 16;" :: "r"(dst), "l"(src))
#define CPC() asm volatile("cp.async.commit_group;")
#define CPW(n) asm volatile("cp.async.wait_group %0;" :: "n"(n))

// ---------------- fused prep ----------------
__global__ void prep_kernel(const float* __restrict__ q1w, const float* __restrict__ q2w,
                            const float* __restrict__ kv2w, const float* __restrict__ lepew,
                            const float* __restrict__ q1b, const float* __restrict__ q2b,
                            const float* __restrict__ kv2b, const float* __restrict__ lepeb,
                            const float* __restrict__ kv1w, const float* __restrict__ projw,
                            const float* __restrict__ srw,
                            float* __restrict__ wbig, float* __restrict__ bbig,
                            float* __restrict__ wkv1, float* __restrict__ wproj,
                            float* __restrict__ srwt,
                            float* __restrict__ gacc, float* __restrict__ lmacc)
{
    int idx = blockIdx.x * blockDim.x + threadIdx.x;   // 262144
    {
        int o = idx & 255, f = idx >> 8, c = f & 255, q = f >> 8;
        srwt[idx] = f2tff(srw[(o << 10) + (c << 2) + q]);
    }
    if (idx < 196608) {
        int j = idx % 768, k = idx / 768;
        float v;
        if (j < 128)      v = q1w[k * 128 + j];
        else if (j < 256) v = q2w[k * 128 + j - 128];
        else if (j < 512) v = kv2w[k * 256 + j - 256];
        else              v = lepew[k * 256 + j - 512];
        wbig[idx] = f2tff(v);
        if (k == 0) {
            float bv;
            if (j < 128)      bv = q1b[j];
            else if (j < 256) bv = q2b[j - 128];
            else if (j < 512) bv = kv2b[j - 256];
            else              bv = lepeb[j - 512];
            bbig[j] = bv;
        }
    }
    if (idx < 65536) {
        wkv1[idx]  = f2tff(kv1w[idx]);
        wproj[idx] = f2tff(projw[idx]);
    }
    if (idx < 16384) lmacc[idx] = 0.f;
    if (idx < 4096)  gacc[idx]  = 0.f;
}

// ---------------- pipelined tf32 GEMM core ----------------
template<int FUSE, int XCOL>
__device__ __forceinline__ void gemm_core(
    const float* __restrict__ A, const float* __restrict__ A2,
    const float* __restrict__ Bw, const float* __restrict__ bias,
    float* __restrict__ C, int K, int Nn, float oscale, int oround,
    int bx, int by, float* smx)
{
    float* As = smx;                   // [2][128*36]
    float* Bs = smx + 2 * 4608;        // [2][32*136]
    float* biass = smx + 2 * 4608 + 2 * 4352;
    const int tid = threadIdx.x, warp = tid >> 5, lane = tid & 31;
    const int m0 = by * 128, n0 = bx * 128;
    const int wm = (warp & 1) * 64, wn = (warp >> 1) * 32;
    if (tid < 128) biass[tid] = bias[n0 + tid];

    float acc[4][4][4];
#pragma unroll
    for (int i = 0; i < 4; ++i)
#pragma unroll
        for (int j = 0; j < 4; ++j)
#pragma unroll
            for (int k = 0; k < 4; ++k) acc[i][j][k] = 0.f;

    const int am = tid >> 1, akb = (tid & 1) * 16;
    const int bk = tid >> 3, bnb = (tid & 7) * 16;
    const int row = m0 + am;
    const int xb = row >> 10, xm = row & 1023;
    const int ii2 = (xm >> 5) << 1, jj2 = (xm & 31) << 1;
    const int basepix = xb << 12;

    const float* Ap  = A + (size_t)row * K + akb;
    const float* A2p = FUSE ? (A2 + (size_t)row * K + akb) : (const float*)0;
    const float* Bp  = Bw + (size_t)bk * Nn + n0 + bnb;
    const unsigned BsW = sptr(Bs) + (bk * 136 + bnb) * 4;

    float4 ar[4], ar2[4];
#pragma unroll
    for (int i = 0; i < 4; ++i) {
        if (XCOL) {
            int k = akb + i * 4, f = k >> 8, cc = k & 255;
            int n = ((ii2 + (f >> 1)) << 6) + jj2 + (f & 1);
            ar[i] = *(const float4*)&A[(size_t)(basepix + n) * 256 + cc];
        } else {
            ar[i] = *(const float4*)(Ap + i * 4);
        }
    }
    if (FUSE) {
#pragma unroll
        for (int i = 0; i < 4; ++i) ar2[i] = *(const float4*)(A2p + i * 4);
    }
#pragma unroll
    for (int i = 0; i < 4; ++i) CPA(BsW + i * 16, Bp + i * 4);
    CPC();

    const int nc = K >> 5;
    for (int c = 0; c < nc; ++c) {
        const int buf = c & 1;
        CPW(0);
        {
            float* dst = As + buf * 4608 + am * 36 + akb;
#pragma unroll
            for (int i = 0; i < 4; ++i) {
                float4 v = ar[i];
                if (FUSE) { float4 w = ar2[i]; v.x += w.x; v.y += w.y; v.z += w.z; v.w += w.w; }
                dst[i * 4 + 0] = f2tff(v.x); dst[i * 4 + 1] = f2tff(v.y);
                dst[i * 4 + 2] = f2tff(v.z); dst[i * 4 + 3] = f2tff(v.w);
            }
        }
        __syncthreads();
        if (c + 1 < nc) {
            const float* bp = Bp + (size_t)(c + 1) * 32 * Nn;
            unsigned w = BsW + (buf ^ 1) * (4352 * 4);
#pragma unroll
            for (int i = 0; i < 4; ++i) CPA(w + i * 16, bp + i * 4);
            CPC();
#pragma unroll
            for (int i = 0; i < 4; ++i) {
                if (XCOL) {
                    int k = (c + 1) * 32 + akb + i * 4, f = k >> 8, cc = k & 255;
                    int n = ((ii2 + (f >> 1)) << 6) + jj2 + (f & 1);
                    ar[i] = *(const float4*)&A[(size_t)(basepix + n) * 256 + cc];
                } else {
                    ar[i] = *(const float4*)(Ap + (c + 1) * 32 + i * 4);
                }
            }
            if (FUSE) {
                const float* a2p = A2p + (c + 1) * 32;
#pragma unroll
                for (int i = 0; i < 4; ++i) ar2[i] = *(const float4*)(a2p + i * 4);
            }
        }
        const float* Ab = As + buf * 4608;
        const float* Bb = Bs + buf * 4352;
#pragma unroll
        for (int ks = 0; ks < 4; ++ks) {
            unsigned a[4][4], bfr[4][2];
#pragma unroll
            for (int mt = 0; mt < 4; ++mt) {
                int r = wm + mt * 16 + (lane >> 2), cc = ks * 8 + (lane & 3);
                a[mt][0] = __float_as_uint(Ab[r * 36 + cc]);
                a[mt][1] = __float_as_uint(Ab[(r + 8) * 36 + cc]);
                a[mt][2] = __float_as_uint(Ab[r * 36 + cc + 4]);
                a[mt][3] = __float_as_uint(Ab[(r + 8) * 36 + cc + 4]);
            }
#pragma unroll
            for (int nt = 0; nt < 4; ++nt) {
                int n = wn + nt * 8 + (lane >> 2), kr = ks * 8 + (lane & 3);
                bfr[nt][0] = __float_as_uint(Bb[kr * 136 + n]);
                bfr[nt][1] = __float_as_uint(Bb[(kr + 4) * 136 + n]);
            }
#pragma unroll
            for (int mt = 0; mt < 4; ++mt)
#pragma unroll
                for (int nt = 0; nt < 4; ++nt) mma8(acc[mt][nt], a[mt], bfr[nt]);
        }
    }

#pragma unroll
    for (int mt = 0; mt < 4; ++mt) {
        int r = m0 + wm + mt * 16 + (lane >> 2);
#pragma unroll
        for (int nt = 0; nt < 4; ++nt) {
            int cc = wn + nt * 8 + (lane & 3) * 2;
            float o0 = (acc[mt][nt][0] + biass[cc]) * oscale;
            float o1 = (acc[mt][nt][1] + biass[cc + 1]) * oscale;
            float o2 = (acc[mt][nt][2] + biass[cc]) * oscale;
            float o3 = (acc[mt][nt][3] + biass[cc + 1]) * oscale;
            if (oround) { o0 = f2tff(o0); o1 = f2tff(o1); o2 = f2tff(o2); o3 = f2tff(o3); }
            *(float2*)&C[(size_t)r * Nn + n0 + cc] = make_float2(o0, o1);
            *(float2*)&C[(size_t)(r + 8) * Nn + n0 + cc] = make_float2(o2, o3);
        }
    }
}

// ---------------- mega1: big linear GEMM || sr conv GEMM (im2col fused) ----------------
__global__ __launch_bounds__(256, 2) void mega1_kernel(
    const float* __restrict__ x,
    const float* __restrict__ wbig, const float* __restrict__ bbig, float* __restrict__ big,
    const float* __restrict__ srwt, const float* __restrict__ srb, float* __restrict__ xs)
{
    extern __shared__ float smx[];
    if (blockIdx.x < 6) {
        gemm_core<0, 0>(x, nullptr, wbig, bbig, big, 256, 768, 1.f, 1,
                        blockIdx.x, blockIdx.y, smx);
    } else if (blockIdx.y < 32) {
        gemm_core<0, 1>(x, nullptr, srwt, srb, xs, 1024, 256, 1.f, 0,
                        blockIdx.x - 6, blockIdx.y, smx);
    }
}

// ---------------- kv1ln: fused LayerNorm+GELU+GEMM ----------------
__global__ __launch_bounds__(256, 2) void kv1ln_kernel(
    const float* __restrict__ xs, const float* __restrict__ wkv1,
    const float* __restrict__ kv1b, const float* __restrict__ normw,
    const float* __restrict__ normb, float* __restrict__ kv1)
{
    extern __shared__ float smx[];
    float* xt = smx;                       // 16640
    float* Bs = smx + 16640;               // 8704
    float* biass = smx + 16640 + 8704;     // 128
    const int tid = threadIdx.x, warp = tid >> 5, lane = tid & 31;
    const int m0 = blockIdx.y * 64, n0 = blockIdx.x * 128;
    if (tid < 128) biass[tid] = kv1b[n0 + tid];

    const int r = tid >> 2, cq = (tid & 3) * 64;
    {
        const float* src = xs + (size_t)(m0 + r) * 256 + cq;
#pragma unroll
        for (int i = 0; i < 16; ++i)
            *(float4*)&xt[r * 260 + cq + i * 4] = *(const float4*)(src + i * 4);
    }
    __syncthreads();

    {
        float s = 0.f, s2 = 0.f;
#pragma unroll
        for (int i = 0; i < 64; ++i) { float v = xt[r * 260 + cq + i]; s += v; s2 += v * v; }
        s  += __shfl_xor_sync(0xffffffffu, s, 1);  s  += __shfl_xor_sync(0xffffffffu, s, 2);
        s2 += __shfl_xor_sync(0xffffffffu, s2, 1); s2 += __shfl_xor_sync(0xffffffffu, s2, 2);
        float mean = s * (1.f / 256.f);
        float var = s2 * (1.f / 256.f) - mean * mean;
        float inv = rsqrtf(var + 1e-5f);
#pragma unroll 8
        for (int i = 0; i < 64; ++i) {
            int c = cq + i;
            float y = (xt[r * 260 + c] - mean) * inv * normw[c] + normb[c];
            xt[r * 260 + c] = f2tff(0.5f * y * (1.0f + erff(y * 0.70710678118654752f)));
        }
    }
    __syncthreads();

    const int wm = (warp & 1) * 32, wn = (warp >> 1) * 32;
    float acc[2][4][4];
#pragma unroll
    for (int i = 0; i < 2; ++i)
#pragma unroll
        for (int j = 0; j < 4; ++j)
#pragma unroll
            for (int k = 0; k < 4; ++k) acc[i][j][k] = 0.f;

    const int bk = tid >> 3, bnb = (tid & 7) * 16;
    const float* Bp = wkv1 + (size_t)bk * 256 + n0 + bnb;
    const unsigned BsW = sptr(Bs) + (bk * 136 + bnb) * 4;
#pragma unroll
    for (int i = 0; i < 4; ++i) CPA(BsW + i * 16, Bp + i * 4);
    CPC();

    for (int c = 0; c < 8; ++c) {
        const int buf = c & 1;
        CPW(0);
        __syncthreads();
        if (c < 7) {
            const float* bp = Bp + (size_t)(c + 1) * 32 * 256;
            unsigned w = BsW + (buf ^ 1) * (4352 * 4);
#pragma unroll
            for (int i = 0; i < 4; ++i) CPA(w + i * 16, bp + i * 4);
            CPC();
        }
        const float* Bb = Bs + buf * 4352;
#pragma unroll
        for (int ks = 0; ks < 4; ++ks) {
            unsigned a[2][4], bfr[4][2];
#pragma unroll
            for (int mt = 0; mt < 2; ++mt) {
                int rr = wm + mt * 16 + (lane >> 2), cc = c * 32 + ks * 8 + (lane & 3);
                a[mt][0] = __float_as_uint(xt[rr * 260 + cc]);
                a[mt][1] = __float_as_uint(xt[(rr + 8) * 260 + cc]);
                a[mt][2] = __float_as_uint(xt[rr * 260 + cc + 4]);
                a[mt][3] = __float_as_uint(xt[(rr + 8) * 260 + cc + 4]);
            }
#pragma unroll
            for (int nt = 0; nt < 4; ++nt) {
                int n = wn + nt * 8 + (lane >> 2), kr = ks * 8 + (lane & 3);
                bfr[nt][0] = __float_as_uint(Bb[kr * 136 + n]);
                bfr[nt][1] = __float_as_uint(Bb[(kr + 4) * 136 + n]);
            }
#pragma unroll
            for (int mt = 0; mt < 2; ++mt)
#pragma unroll
                for (int nt = 0; nt < 4; ++nt) mma8(acc[mt][nt], a[mt], bfr[nt]);
        }
        __syncthreads();
    }

#pragma unroll
    for (int mt = 0; mt < 2; ++mt) {
        int rr = m0 + wm + mt * 16 + (lane >> 2);
#pragma unroll
        for (int nt = 0; nt < 4; ++nt) {
            int cc = wn + nt * 8 + (lane & 3) * 2;
            float o0 = f2tff(acc[mt][nt][0] + biass[cc]);
            float o1 = f2tff(acc[mt][nt][1] + biass[cc + 1]);
            float o2 = f2tff(acc[mt][nt][2] + biass[cc]);
            float o3 = f2tff(acc[mt][nt][3] + biass[cc + 1]);
            *(float2*)&kv1[(size_t)rr * 256 + n0 + cc] = make_float2(o0, o1);
            *(float2*)&kv1[(size_t)(rr + 8) * 256 + n0 + cc] = make_float2(o2, o3);
        }
    }
}

// ---------------- mega3: attn1 (64q tiles, reg-resident P) || attn2 || dwconv ----------------
// attn1 smem (floats): qs[64*36]=2304 | kb 2x4608 | vb 2x4608 | mzw 256 | mzf 128 | gcol 1024 | op 2176
#define QS_O  0
#define KB_O  2304
#define VB_O  11520
#define MZW_O 20736
#define MZF_O 20992
#define GC_O  21120
#define OP_O  22144
#define M3_SMEM_FLOATS 24320

__global__ __launch_bounds__(256, 2) void mega3_kernel(
    const float* __restrict__ big, const float* __restrict__ kv1,
    float* __restrict__ att_out, float* __restrict__ gacc, float* __restrict__ lmacc,
    const float* __restrict__ cw, const float* __restrict__ cb, float* __restrict__ lepe)
{
    extern __shared__ float sm[];
    const int bid = blockIdx.x;
    const int tid = threadIdx.x;

    if (bid < 1024) {
        // ============ attn1: 64 queries per block, pass1 stats + pass2 PV ============
        float* qs   = sm + QS_O;
        float* kb   = sm + KB_O;
        float* vb   = sm + VB_O;
        float2* mzw = (float2*)(sm + MZW_O);   // [2][64]
        float2* mzf = (float2*)(sm + MZF_O);   // [64]
        float* gcol = sm + GC_O;               // 1024
        float* op   = sm + OP_O;               // 64x34

        const int warp = tid >> 5, lane = tid & 31;
        const int bh = bid >> 6, b = bh >> 2, h = bh & 3;
        const int q0 = (bid & 63) * 64;
        const int wq = warp & 3, wk = warp >> 2;

        for (int i = tid; i < 1024; i += 256) gcol[i] = 0.f;
        // stage Q: 64 rows x 32 d (pre-rounded tf32)
        {
            int q = tid >> 2, d8 = (tid & 3) * 8;
            const float* src = &big[(size_t)(b * 4096 + q0 + q) * 768 + h * 32 + d8];
            *(float4*)&qs[q * 36 + d8]     = *(const float4*)(src);
            *(float4*)&qs[q * 36 + d8 + 4] = *(const float4*)(src + 4);
        }
        const int jj = tid >> 1, db = (tid & 1) * 16;
        const size_t kbase = (size_t)(b * 1024) * 256 + h * 32;
        const size_t vbase = kbase + 128;
        const unsigned kW = sptr(kb) + (jj * 36 + db) * 4;
        const unsigned vW = sptr(vb) + (jj * 36 + db) * 4;
        // prefetch K chunk 0
        {
            const float* src = kv1 + kbase + (size_t)jj * 256 + db;
#pragma unroll
            for (int i = 0; i < 4; ++i) CPA(kW + i * 16, src + i * 4);
            CPC();
        }
        __syncthreads();

        unsigned qa[4][4];
#pragma unroll
        for (int ks = 0; ks < 4; ++ks) {
            int r = wq * 16 + (lane >> 2), cc = ks * 8 + (lane & 3);
            qa[ks][0] = __float_as_uint(qs[r * 36 + cc]);
            qa[ks][1] = __float_as_uint(qs[(r + 8) * 36 + cc]);
            qa[ks][2] = __float_as_uint(qs[r * 36 + cc + 4]);
            qa[ks][3] = __float_as_uint(qs[(r + 8) * 36 + cc + 4]);
        }

        // ---- pass 1: online (m,z) per thread, K only ----
        float m0 = -1e30f, z0 = 0.f, m1 = -1e30f, z1 = 0.f;
        for (int ch = 0; ch < 8; ++ch) {
            if (ch < 7) {
                const float* src = kv1 + kbase + (size_t)((ch + 1) * 128 + jj) * 256 + db;
                unsigned w = kW + ((ch + 1) & 1) * (4608 * 4);
#pragma unroll
                for (int i = 0; i < 4; ++i) CPA(w + i * 16, src + i * 4);
                CPC();
                CPW(1);
            } else {
                CPW(0);
            }
            __syncthreads();
            const float* kc = kb + (ch & 1) * 4608;
#pragma unroll
            for (int g = 0; g < 8; ++g) {
                float c4[4] = {0.f, 0.f, 0.f, 0.f};
                int nb = wk * 64 + g * 8;
#pragma unroll
                for (int ks = 0; ks < 4; ++ks) {
                    int n = nb + (lane >> 2), dr = ks * 8 + (lane & 3);
                    unsigned bb2[2] = { __float_as_uint(kc[n * 36 + dr]),
                                        __float_as_uint(kc[n * 36 + dr + 4]) };
                    mma8(c4, qa[ks], bb2);
                }
                float s0 = c4[0] * SCALE, s1 = c4[1] * SCALE;
                float s2 = c4[2] * SCALE, s3 = c4[3] * SCALE;
                float nm = fmaxf(m0, fmaxf(s0, s1));
                z0 = z0 * __expf(m0 - nm) + __expf(s0 - nm) + __expf(s1 - nm);
                m0 = nm;
                nm = fmaxf(m1, fmaxf(s2, s3));
                z1 = z1 * __expf(m1 - nm) + __expf(s2 - nm) + __expf(s3 - nm);
                m1 = nm;
            }
            __syncthreads();
        }
        // lane-merge over the 4 lanes of each row quad
#pragma unroll
        for (int o = 1; o <= 2; o <<= 1) {
            float om = __shfl_xor_sync(0xffffffffu, m0, o), oz = __shfl_xor_sync(0xffffffffu, z0, o);
            float nm = fmaxf(m0, om);
            z0 = z0 * __expf(m0 - nm) + oz * __expf(om - nm); m0 = nm;
            om = __shfl_xor_sync(0xffffffffu, m1, o); oz = __shfl_xor_sync(0xffffffffu, z1, o);
            nm = fmaxf(m1, om);
            z1 = z1 * __expf(m1 - nm) + oz * __expf(om - nm); m1 = nm;
        }
        if ((lane & 3) == 0) {
            int r = wq * 16 + (lane >> 2);
            mzw[wk * 64 + r] = make_float2(m0, z0);
            mzw[wk * 64 + r + 8] = make_float2(m1, z1);
        }
        __syncthreads();
        // prefetch pass-2 chunk 0 (K into buf0, V into buf0)
        {
            const float* sk = kv1 + kbase + (size_t)jj * 256 + db;
            const float* sv = kv1 + vbase + (size_t)jj * 256 + db;
#pragma unroll
            for (int i = 0; i < 4; ++i) CPA(kW + i * 16, sk + i * 4);
#pragma unroll
            for (int i = 0; i < 4; ++i) CPA(vW + i * 16, sv + i * 4);
            CPC();
        }
        if (tid < 64) {
            float2 A = mzw[tid], B = mzw[64 + tid];
            float M = fmaxf(A.x, B.x);
            float Z = A.y * __expf(A.x - M) + B.y * __expf(B.x - M);
            mzf[tid] = make_float2(M, 1.f / Z);
        }
        __syncthreads();

        const float2 mzr0 = mzf[wq * 16 + (lane >> 2)];
        const float2 mzr1 = mzf[wq * 16 + (lane >> 2) + 8];
        const int t = lane & 3;
        const int sl0 = (lane & ~3) | (t >> 1), sl1 = sl0 + 2;

        // ---- pass 2: QK -> exp -> shfl-permute -> PV, P never touches smem ----
        float o4[4][4];
#pragma unroll
        for (int nt = 0; nt < 4; ++nt)
#pragma unroll
            for (int k = 0; k < 4; ++k) o4[nt][k] = 0.f;

        for (int ch = 0; ch < 8; ++ch) {
            if (ch < 7) {
                const float* sk = kv1 + kbase + (size_t)((ch + 1) * 128 + jj) * 256 + db;
                const float* sv = kv1 + vbase + (size_t)((ch + 1) * 128 + jj) * 256 + db;
                unsigned wk_ = kW + ((ch + 1) & 1) * (4608 * 4);
                unsigned wv_ = vW + ((ch + 1) & 1) * (4608 * 4);
#pragma unroll
                for (int i = 0; i < 4; ++i) CPA(wk_ + i * 16, sk + i * 4);
#pragma unroll
                for (int i = 0; i < 4; ++i) CPA(wv_ + i * 16, sv + i * 4);
                CPC();
                CPW(1);
            } else {
                CPW(0);
            }
            __syncthreads();
            const float* kc = kb + (ch & 1) * 4608;
            const float* vc = vb + (ch & 1) * 4608;
#pragma unroll
            for (int g = 0; g < 8; ++g) {
                float c4[4] = {0.f, 0.f, 0.f, 0.f};
                const int nb = wk * 64 + g * 8;
#pragma unroll
                for (int ks = 0; ks < 4; ++ks) {
                    int n = nb + (lane >> 2), dr = ks * 8 + (lane & 3);
                    unsigned bb2[2] = { __float_as_uint(kc[n * 36 + dr]),
                                        __float_as_uint(kc[n * 36 + dr + 4]) };
                    mma8(c4, qa[ks], bb2);
                }
                float p0 = f2tff(__expf(c4[0] * SCALE - mzr0.x) * mzr0.y);
                float p1 = f2tff(__expf(c4[1] * SCALE - mzr0.x) * mzr0.y);
                float p2 = f2tff(__expf(c4[2] * SCALE - mzr1.x) * mzr1.y);
                float p3 = f2tff(__expf(c4[3] * SCALE - mzr1.x) * mzr1.y);
                // permute C-frag (cols 2t,2t+1) -> A-frag (cols t, t+4)
                float u00 = __shfl_sync(0xffffffffu, p0, sl0);
                float u01 = __shfl_sync(0xffffffffu, p1, sl0);
                float u02 = __shfl_sync(0xffffffffu, p0, sl1);
                float u03 = __shfl_sync(0xffffffffu, p1, sl1);
                float v00 = __shfl_sync(0xffffffffu, p2, sl0);
                float v01 = __shfl_sync(0xffffffffu, p3, sl0);
                float v02 = __shfl_sync(0xffffffffu, p2, sl1);
                float v03 = __shfl_sync(0xffffffffu, p3, sl1);
                float a0 = (t & 1) ? u01 : u00;   // row r,   col t
                float a1 = (t & 1) ? v01 : v00;   // row r+8, col t
                float a2 = (t & 1) ? u03 : u02;   // row r,   col t+4
                float a3 = (t & 1) ? v03 : v02;   // row r+8, col t+4
                // gcol: column sums over this warp's 16 rows
                float st  = a0 + a1;
                float st4 = a2 + a3;
#pragma unroll
                for (int o = 4; o <= 16; o <<= 1) {
                    st  += __shfl_xor_sync(0xffffffffu, st, o);
                    st4 += __shfl_xor_sync(0xffffffffu, st4, o);
                }
                if (lane < 4) {
                    atomicAdd(&gcol[ch * 128 + nb + lane], st);
                    atomicAdd(&gcol[ch * 128 + nb + lane + 4], st4);
                }
                // PV
                unsigned af[4] = { __float_as_uint(a0), __float_as_uint(a1),
                                   __float_as_uint(a2), __float_as_uint(a3) };
#pragma unroll
                for (int nt = 0; nt < 4; ++nt) {
                    int jl = nb + (lane & 3);
                    int d = nt * 8 + (lane >> 2);
                    unsigned bb2[2] = { __float_as_uint(vc[jl * 36 + d]),
                                        __float_as_uint(vc[(jl + 4) * 36 + d]) };
                    mma8(o4[nt], af, bb2);
                }
            }
            __syncthreads();
        }

        // reduce partial O over the 2 key-split warps
        if (wk == 1) {
#pragma unroll
            for (int nt = 0; nt < 4; ++nt) {
                int rr = wq * 16 + (lane >> 2), col = nt * 8 + (lane & 3) * 2;
                *(float2*)&op[rr * 34 + col] = make_float2(o4[nt][0], o4[nt][1]);
                *(float2*)&op[(rr + 8) * 34 + col] = make_float2(o4[nt][2], o4[nt][3]);
            }
        }
        __syncthreads();
        if (wk == 0) {
#pragma unroll
            for (int nt = 0; nt < 4; ++nt) {
                int rr = wq * 16 + (lane >> 2), col = nt * 8 + (lane & 3) * 2;
                float2 e0 = *(float2*)&op[rr * 34 + col];
                float2 e1 = *(float2*)&op[(rr + 8) * 34 + col];
                int gr0 = b * 4096 + q0 + rr, gr1 = gr0 + 8;
                *(float2*)&att_out[(size_t)gr0 * 256 + h * 32 + col] =
                    make_float2(o4[nt][0] + e0.x, o4[nt][1] + e0.y);
                *(float2*)&att_out[(size_t)gr1 * 256 + h * 32 + col] =
                    make_float2(o4[nt][2] + e1.x, o4[nt][3] + e1.y);
            }
        }
        // flush gcol
        for (int i = tid; i < 1024; i += 256) atomicAdd(&gacc[(b << 10) + i], gcol[i]);
    } else if (bid < 1536) {
        // ============ attn2: 4x4 window attention ============
        if (tid >= 128) return;
        float* ks = sm;
        float* vs = sm + 8 * 528;
        float* ps = sm + 16 * 528;
        const int g = tid >> 4, t = tid & 15;
        const int w = ((bid - 1024) << 3) + g;
        const int b = w >> 10, h = (w >> 8) & 3, win = w & 255;
        const int wy = win >> 4, wx = win & 15;
        const int n = ((wy << 2) + (t >> 2)) * 64 + (wx << 2) + (t & 3);

        const float* row = &big[((size_t)(b * 4096 + n)) * 768];
        float qr[32];
#pragma unroll
        for (int dd = 0; dd < 32; ++dd) {
            ks[(g * 16 + t) * 33 + dd] = row[256 + h * 32 + dd];
            vs[(g * 16 + t) * 33 + dd] = row[384 + h * 32 + dd];
            qr[dd] = row[128 + h * 32 + dd];
        }
        __syncwarp(0xffffffffu);

        float s[16];
        float mx = -1e30f;
#pragma unroll
        for (int m = 0; m < 16; ++m) {
            float a = 0.f;
#pragma unroll
            for (int dd = 0; dd < 32; ++dd) a += qr[dd] * ks[(g * 16 + m) * 33 + dd];
            s[m] = a * SCALE;
            mx = fmaxf(mx, s[m]);
        }
        float sum = 0.f;
#pragma unroll
        for (int m = 0; m < 16; ++m) { s[m] = __expf(s[m] - mx); sum += s[m]; }
        float inv = 1.f / sum;

        float o[32];
#pragma unroll
        for (int dd = 0; dd < 32; ++dd) o[dd] = 0.f;
#pragma unroll
        for (int m = 0; m < 16; ++m) {
            float p = s[m] * inv;
            ps[(g * 16 + t) * 17 + m] = p;
#pragma unroll
            for (int dd = 0; dd < 32; ++dd) o[dd] += p * vs[(g * 16 + m) * 33 + dd];
        }
        float* orow = &att_out[((size_t)(b * 4096 + n)) * 256 + 128 + h * 32];
#pragma unroll
        for (int dd = 0; dd < 32; ++dd) orow[dd] = o[dd];
        __syncwarp(0xffffffffu);

        float cs = 0.f;
#pragma unroll
        for (int qq = 0; qq < 16; ++qq) cs += ps[(g * 16 + qq) * 17 + t];
        atomicAdd(&lmacc[((b << 8) + win) * 16 + t], cs);
    } else {
        // ============ dwconv: lepe depthwise 3x3 ============
        int idx = (bid - 1536) * 256 + tid;  // BB*NN*64
        int c4i = idx & 63;
        int n = (idx >> 6) & 4095;
        int b = idx >> 18;
        int y = n >> 6, x = n & 63;
        int c = c4i << 2;
        float4 acc = make_float4(cb[c], cb[c + 1], cb[c + 2], cb[c + 3]);
#pragma unroll
        for (int dy = 0; dy < 3; ++dy) {
            int yy = y + dy - 1;
            if ((unsigned)yy >= 64u) continue;
#pragma unroll
            for (int dx = 0; dx < 3; ++dx) {
                int xx = x + dx - 1;
                if ((unsigned)xx >= 64u) continue;
                float4 v = *(const float4*)&big[((size_t)((b << 12) + (yy << 6) + xx)) * 768 + 512 + c];
                int wi = dy * 3 + dx;
                acc.x += v.x * cw[(c + 0) * 9 + wi];
                acc.y += v.y * cw[(c + 1) * 9 + wi];
                acc.z += v.z * cw[(c + 2) * 9 + wi];
                acc.w += v.w * cw[(c + 3) * 9 + wi];
            }
        }
        *(float4*)&lepe[((size_t)((b << 12) + n)) * 256 + c] = acc;
    }
}

// ---------------- projmask: final projection GEMM || mask assembly ----------------
__global__ __launch_bounds__(256, 2) void projmask_kernel(
    const float* __restrict__ att, const float* __restrict__ lepe,
    const float* __restrict__ wproj, const float* __restrict__ projb,
    float* __restrict__ out,
    const float* __restrict__ gacc, const float* __restrict__ lmacc)
{
    extern __shared__ float smx[];
    if (blockIdx.x < 2) {
        gemm_core<1, 0>(att, lepe, wproj, projb, out, 256, 256, 2.f, 0,
                        blockIdx.x, blockIdx.y, smx);
    } else if (blockIdx.y < 64) {
        int idx = blockIdx.y * 256 + threadIdx.x;
        int b = idx >> 12, n = idx & 4095;
        int y = n >> 6, x = n & 63;
        float gv = gacc[(b << 10) + ((y >> 1) << 5) + (x >> 1)] * (1.f / 16384.f);
        float lv = lmacc[((b << 8) + ((y >> 2) << 4) + (x >> 2)) * 16 + ((y & 3) << 2) + (x & 3)] * (1.f / 64.f);
        float m = gv + lv;
        out[4194304 + (b << 12) + (y << 6) + x] = m;
        out[4210688 + (b << 12) + (x << 6) + y] = m;
    }
}

// ---------------- host launcher ----------------
extern "C" void kernel_launch(void* const* d_in, const int* in_sizes, int n_in,
                              void* d_out, int out_size)
{
    const float* x        = (const float*)d_in[0];
    const float* q1_w     = (const float*)d_in[1];
    const float* q1_b     = (const float*)d_in[2];
    const float* kv1_w    = (const float*)d_in[3];
    const float* kv1_b    = (const float*)d_in[4];
    const float* q2_w     = (const float*)d_in[5];
    const float* q2_b     = (const float*)d_in[6];
    const float* kv2_w    = (const float*)d_in[7];
    const float* kv2_b    = (const float*)d_in[8];
    const float* lepe_w   = (const float*)d_in[9];
    const float* lepe_b   = (const float*)d_in[10];
    const float* lepe_cw  = (const float*)d_in[11];
    const float* lepe_cb  = (const float*)d_in[12];
    const float* sr_w     = (const float*)d_in[13];
    const float* sr_b     = (const float*)d_in[14];
    const float* norm_w   = (const float*)d_in[15];
    const float* norm_b   = (const float*)d_in[16];
    const float* proj_w   = (const float*)d_in[17];
    const float* proj_b   = (const float*)d_in[18];
    float* out = (float*)d_out;

    float *p_big, *p_lepe, *p_srwt, *p_xs, *p_kv1, *p_att, *p_g, *p_lm;
    float *p_wbig, *p_bbig, *p_wkv1, *p_wproj;
    cudaGetSymbolAddress((void**)&p_big,   g_big);
    cudaGetSymbolAddress((void**)&p_lepe,  g_lepe);
    cudaGetSymbolAddress((void**)&p_srwt,  g_srwt);
    cudaGetSymbolAddress((void**)&p_xs,    g_xs);
    cudaGetSymbolAddress((void**)&p_kv1,   g_kv1);
    cudaGetSymbolAddress((void**)&p_att,   g_att);
    cudaGetSymbolAddress((void**)&p_g,     g_gacc);
    cudaGetSymbolAddress((void**)&p_lm,    g_lmacc);
    cudaGetSymbolAddress((void**)&p_wbig,  g_wbig);
    cudaGetSymbolAddress((void**)&p_bbig,  g_bbig);
    cudaGetSymbolAddress((void**)&p_wkv1,  g_wkv1);
    cudaGetSymbolAddress((void**)&p_wproj, g_wproj);

    const int gsm = (2 * 4608 + 2 * 4352 + 128) * (int)sizeof(float);  // 72192 B
    cudaFuncSetAttribute(mega1_kernel,    cudaFuncAttributeMaxDynamicSharedMemorySize, gsm);
    cudaFuncSetAttribute(projmask_kernel, cudaFuncAttributeMaxDynamicSharedMemorySize, gsm);
    const int ksm = (16640 + 8704 + 128) * (int)sizeof(float);         // 101888 B
    cudaFuncSetAttribute(kv1ln_kernel,    cudaFuncAttributeMaxDynamicSharedMemorySize, ksm);
    const int m3sm = M3_SMEM_FLOATS * (int)sizeof(float);              // 97280 B
    cudaFuncSetAttribute(mega3_kernel,    cudaFuncAttributeMaxDynamicSharedMemorySize, m3sm);

    // 1. fused prep
    prep_kernel<<<1024, 256>>>(q1_w, q2_w, kv2_w, lepe_w, q1_b, q2_b, kv2_b, lepe_b,
                               kv1_w, proj_w, sr_w,
                               p_wbig, p_bbig, p_wkv1, p_wproj, p_srwt, p_g, p_lm);

    // 2. big linear GEMM || sr conv GEMM
    mega1_kernel<<<dim3(8, 128), 256, gsm>>>(x, p_wbig, p_bbig, p_big, p_srwt, sr_b, p_xs);

    // 3. fused LN+GELU+kv1 GEMM
    kv1ln_kernel<<<dim3(2, 64), 256, ksm>>>(p_xs, p_wkv1, kv1_b, norm_w, norm_b, p_kv1);

    // 4. attn1 (reg-P) || attn2 || dwconv
    mega3_kernel<<<5632, 256, m3sm>>>(p_big, p_kv1, p_att, p_g, p_lm,
                                      lepe_cw, lepe_cb, p_lepe);

    // 5. projection GEMM || mask assembly
    projmask_kernel<<<dim3(3, 128), 256, gsm>>>(p_att, p_lepe, p_wproj, proj_b, out, p_g, p_lm);
}

// round 15
// speedup vs baseline: 1.2788x; 1.1122x over previous
#include <cuda_runtime.h>
#include <cuda_fp16.h>
#include <math.h>

// ---------------- problem constants ----------------
#define BB 4
#define NN 4096
#define N1 1024
#define SCALE 0.17677669529663687f  // 1/sqrt(32)

// ---------------- scratch ----------------
__device__ float g_big [BB*NN*768];   // cols: q1[0,128) q2[128,256) kv2[256,512) lin[512,768)
__device__ float g_lepe[BB*NN*256];
__device__ float g_srwt[1024*256];
__device__ float g_xs  [BB*N1*256];
__device__ float g_kv1 [BB*N1*256];
__device__ float g_att [BB*NN*256];   // x1 in [0,128), x2 in [128,256)
__device__ float g_gacc[BB*N1];
__device__ float g_lmacc[BB*256*16];
__device__ float g_wbig[256*768];
__device__ float g_bbig[768];
__device__ float g_wkv1[256*256];
__device__ float g_wproj[256*256];

// ---------------- helpers ----------------
__device__ __forceinline__ unsigned f2tf(float f) {
    unsigned u;
    asm("cvt.rna.tf32.f32 %0, %1;" : "=r"(u) : "f"(f));
    return u;
}
__device__ __forceinline__ float f2tff(float f) { return __uint_as_float(f2tf(f)); }

__device__ __forceinline__ void mma8(float* d, const unsigned* a, const unsigned* b) {
    asm volatile(
        "mma.sync.aligned.m16n8k8.row.col.f32.tf32.tf32.f32 "
        "{%0,%1,%2,%3}, {%4,%5,%6,%7}, {%8,%9}, {%0,%1,%2,%3};"
        : "+f"(d[0]), "+f"(d[1]), "+f"(d[2]), "+f"(d[3])
        : "r"(a[0]), "r"(a[1]), "r"(a[2]), "r"(a[3]), "r"(b[0]), "r"(b[1]));
}

__device__ __forceinline__ unsigned sptr(const void* p) {
    return (unsigned)__cvta_generic_to_shared(p);
}
#define CPA(dst, src) asm volatile("cp.async.cg.shared.global [%0], [%1], 16;" :: "r"(dst), "l"(src))
#define CPC() asm volatile("cp.async.commit_group;")
#define CPW(n) asm volatile("cp.async.wait_group %0;" :: "n"(n))

// ---------------- fused prep ----------------
__global__ void prep_kernel(const float* __restrict__ q1w, const float* __restrict__ q2w,
                            const float* __restrict__ kv2w, const float* __restrict__ lepew,
                            const float* __restrict__ q1b, const float* __restrict__ q2b,
                            const float* __restrict__ kv2b, const float* __restrict__ lepeb,
                            const float* __restrict__ kv1w, const float* __restrict__ projw,
                            const float* __restrict__ srw,
                            float* __restrict__ wbig, float* __restrict__ bbig,
                            float* __restrict__ wkv1, float* __restrict__ wproj,
                            float* __restrict__ srwt,
                            float* __restrict__ gacc, float* __restrict__ lmacc)
{
    int idx = blockIdx.x * blockDim.x + threadIdx.x;   // 262144
    {
        int o = idx & 255, f = idx >> 8, c = f & 255, q = f >> 8;
        srwt[idx] = f2tff(srw[(o << 10) + (c << 2) + q]);
    }
    if (idx < 196608) {
        int j = idx % 768, k = idx / 768;
        float v;
        if (j < 128)      v = q1w[k * 128 + j];
        else if (j < 256) v = q2w[k * 128 + j - 128];
        else if (j < 512) v = kv2w[k * 256 + j - 256];
        else              v = lepew[k * 256 + j - 512];
        wbig[idx] = f2tff(v);
        if (k == 0) {
            float bv;
            if (j < 128)      bv = q1b[j];
            else if (j < 256) bv = q2b[j - 128];
            else if (j < 512) bv = kv2b[j - 256];
            else              bv = lepeb[j - 512];
            bbig[j] = bv;
        }
    }
    if (idx < 65536) {
        wkv1[idx]  = f2tff(kv1w[idx]);
        wproj[idx] = f2tff(projw[idx]);
    }
    if (idx < 16384) lmacc[idx] = 0.f;
    if (idx < 4096)  gacc[idx]  = 0.f;
}

// ---------------- pipelined tf32 GEMM core ----------------
template<int FUSE, int XCOL>
__device__ __forceinline__ void gemm_core(
    const float* __restrict__ A, const float* __restrict__ A2,
    const float* __restrict__ Bw, const float* __restrict__ bias,
    float* __restrict__ C, int K, int Nn, float oscale, int oround,
    int bx, int by, float* smx)
{
    float* As = smx;                   // [2][128*36]
    float* Bs = smx + 2 * 4608;        // [2][32*136]
    float* biass = smx + 2 * 4608 + 2 * 4352;
    const int tid = threadIdx.x, warp = tid >> 5, lane = tid & 31;
    const int m0 = by * 128, n0 = bx * 128;
    const int wm = (warp & 1) * 64, wn = (warp >> 1) * 32;
    if (tid < 128) biass[tid] = bias[n0 + tid];

    float acc[4][4][4];
#pragma unroll
    for (int i = 0; i < 4; ++i)
#pragma unroll
        for (int j = 0; j < 4; ++j)
#pragma unroll
            for (int k = 0; k < 4; ++k) acc[i][j][k] = 0.f;

    const int am = tid >> 1, akb = (tid & 1) * 16;
    const int bk = tid >> 3, bnb = (tid & 7) * 16;
    const int row = m0 + am;
    const int xb = row >> 10, xm = row & 1023;
    const int ii2 = (xm >> 5) << 1, jj2 = (xm & 31) << 1;
    const int basepix = xb << 12;

    const float* Ap  = A + (size_t)row * K + akb;
    const float* A2p = FUSE ? (A2 + (size_t)row * K + akb) : (const float*)0;
    const float* Bp  = Bw + (size_t)bk * Nn + n0 + bnb;
    const unsigned BsW = sptr(Bs) + (bk * 136 + bnb) * 4;

    float4 ar[4], ar2[4];
#pragma unroll
    for (int i = 0; i < 4; ++i) {
        if (XCOL) {
            int k = akb + i * 4, f = k >> 8, cc = k & 255;
            int n = ((ii2 + (f >> 1)) << 6) + jj2 + (f & 1);
            ar[i] = *(const float4*)&A[(size_t)(basepix + n) * 256 + cc];
        } else {
            ar[i] = *(const float4*)(Ap + i * 4);
        }
    }
    if (FUSE) {
#pragma unroll
        for (int i = 0; i < 4; ++i) ar2[i] = *(const float4*)(A2p + i * 4);
    }
#pragma unroll
    for (int i = 0; i < 4; ++i) CPA(BsW + i * 16, Bp + i * 4);
    CPC();

    const int nc = K >> 5;
    for (int c = 0; c < nc; ++c) {
        const int buf = c & 1;
        CPW(0);
        {
            float* dst = As + buf * 4608 + am * 36 + akb;
#pragma unroll
            for (int i = 0; i < 4; ++i) {
                float4 v = ar[i];
                if (FUSE) { float4 w = ar2[i]; v.x += w.x; v.y += w.y; v.z += w.z; v.w += w.w; }
                dst[i * 4 + 0] = f2tff(v.x); dst[i * 4 + 1] = f2tff(v.y);
                dst[i * 4 + 2] = f2tff(v.z); dst[i * 4 + 3] = f2tff(v.w);
            }
        }
        __syncthreads();
        if (c + 1 < nc) {
            const float* bp = Bp + (size_t)(c + 1) * 32 * Nn;
            unsigned w = BsW + (buf ^ 1) * (4352 * 4);
#pragma unroll
            for (int i = 0; i < 4; ++i) CPA(w + i * 16, bp + i * 4);
            CPC();
#pragma unroll
            for (int i = 0; i < 4; ++i) {
                if (XCOL) {
                    int k = (c + 1) * 32 + akb + i * 4, f = k >> 8, cc = k & 255;
                    int n = ((ii2 + (f >> 1)) << 6) + jj2 + (f & 1);
                    ar[i] = *(const float4*)&A[(size_t)(basepix + n) * 256 + cc];
                } else {
                    ar[i] = *(const float4*)(Ap + (c + 1) * 32 + i * 4);
                }
            }
            if (FUSE) {
                const float* a2p = A2p + (c + 1) * 32;
#pragma unroll
                for (int i = 0; i < 4; ++i) ar2[i] = *(const float4*)(a2p + i * 4);
            }
        }
        const float* Ab = As + buf * 4608;
        const float* Bb = Bs + buf * 4352;
#pragma unroll
        for (int ks = 0; ks < 4; ++ks) {
            unsigned a[4][4], bfr[4][2];
#pragma unroll
            for (int mt = 0; mt < 4; ++mt) {
                int r = wm + mt * 16 + (lane >> 2), cc = ks * 8 + (lane & 3);
                a[mt][0] = __float_as_uint(Ab[r * 36 + cc]);
                a[mt][1] = __float_as_uint(Ab[(r + 8) * 36 + cc]);
                a[mt][2] = __float_as_uint(Ab[r * 36 + cc + 4]);
                a[mt][3] = __float_as_uint(Ab[(r + 8) * 36 + cc + 4]);
            }
#pragma unroll
            for (int nt = 0; nt < 4; ++nt) {
                int n = wn + nt * 8 + (lane >> 2), kr = ks * 8 + (lane & 3);
                bfr[nt][0] = __float_as_uint(Bb[kr * 136 + n]);
                bfr[nt][1] = __float_as_uint(Bb[(kr + 4) * 136 + n]);
            }
#pragma unroll
            for (int mt = 0; mt < 4; ++mt)
#pragma unroll
                for (int nt = 0; nt < 4; ++nt) mma8(acc[mt][nt], a[mt], bfr[nt]);
        }
    }

#pragma unroll
    for (int mt = 0; mt < 4; ++mt) {
        int r = m0 + wm + mt * 16 + (lane >> 2);
#pragma unroll
        for (int nt = 0; nt < 4; ++nt) {
            int cc = wn + nt * 8 + (lane & 3) * 2;
            float o0 = (acc[mt][nt][0] + biass[cc]) * oscale;
            float o1 = (acc[mt][nt][1] + biass[cc + 1]) * oscale;
            float o2 = (acc[mt][nt][2] + biass[cc]) * oscale;
            float o3 = (acc[mt][nt][3] + biass[cc + 1]) * oscale;
            if (oround) { o0 = f2tff(o0); o1 = f2tff(o1); o2 = f2tff(o2); o3 = f2tff(o3); }
            *(float2*)&C[(size_t)r * Nn + n0 + cc] = make_float2(o0, o1);
            *(float2*)&C[(size_t)(r + 8) * Nn + n0 + cc] = make_float2(o2, o3);
        }
    }
}

// ---------------- mega1: big linear GEMM || sr conv GEMM (im2col fused) ----------------
__global__ __launch_bounds__(256, 2) void mega1_kernel(
    const float* __restrict__ x,
    const float* __restrict__ wbig, const float* __restrict__ bbig, float* __restrict__ big,
    const float* __restrict__ srwt, const float* __restrict__ srb, float* __restrict__ xs)
{
    extern __shared__ float smx[];
    if (blockIdx.x < 6) {
        gemm_core<0, 0>(x, nullptr, wbig, bbig, big, 256, 768, 1.f, 1,
                        blockIdx.x, blockIdx.y, smx);
    } else if (blockIdx.y < 32) {
        gemm_core<0, 1>(x, nullptr, srwt, srb, xs, 1024, 256, 1.f, 0,
                        blockIdx.x - 6, blockIdx.y, smx);
    }
}

// ---------------- mega2: kv1ln GEMM || attn2 || dwconv ----------------
// grid: [0,128) kv1ln, [128,640) attn2, [640,4736) dwconv
__global__ __launch_bounds__(256, 2) void mega2_kernel(
    const float* __restrict__ xs, const float* __restrict__ wkv1,
    const float* __restrict__ kv1b, const float* __restrict__ normw,
    const float* __restrict__ normb, float* __restrict__ kv1,
    const float* __restrict__ big, const float* __restrict__ cw,
    const float* __restrict__ cb, float* __restrict__ lepe,
    float* __restrict__ att_out, float* __restrict__ lmacc)
{
    extern __shared__ float smx[];
    const int bid = blockIdx.x;
    const int tid = threadIdx.x;

    if (bid < 128) {
        // ---- kv1ln: LN+GELU fused into kv1 GEMM ----
        float* xt = smx;                       // 16640
        float* Bs = smx + 16640;               // 8704
        float* biass = smx + 16640 + 8704;     // 128
        const int warp = tid >> 5, lane = tid & 31;
        const int m0 = (bid >> 1) * 64, n0 = (bid & 1) * 128;
        if (tid < 128) biass[tid] = kv1b[n0 + tid];

        const int r = tid >> 2, cq = (tid & 3) * 64;
        {
            const float* src = xs + (size_t)(m0 + r) * 256 + cq;
#pragma unroll
            for (int i = 0; i < 16; ++i)
                *(float4*)&xt[r * 260 + cq + i * 4] = *(const float4*)(src + i * 4);
        }
        __syncthreads();

        {
            float s = 0.f, s2 = 0.f;
#pragma unroll
            for (int i = 0; i < 64; ++i) { float v = xt[r * 260 + cq + i]; s += v; s2 += v * v; }
            s  += __shfl_xor_sync(0xffffffffu, s, 1);  s  += __shfl_xor_sync(0xffffffffu, s, 2);
            s2 += __shfl_xor_sync(0xffffffffu, s2, 1); s2 += __shfl_xor_sync(0xffffffffu, s2, 2);
            float mean = s * (1.f / 256.f);
            float var = s2 * (1.f / 256.f) - mean * mean;
            float inv = rsqrtf(var + 1e-5f);
#pragma unroll 8
            for (int i = 0; i < 64; ++i) {
                int c = cq + i;
                float y = (xt[r * 260 + c] - mean) * inv * normw[c] + normb[c];
                xt[r * 260 + c] = f2tff(0.5f * y * (1.0f + erff(y * 0.70710678118654752f)));
            }
        }
        __syncthreads();

        const int wm = (warp & 1) * 32, wn = (warp >> 1) * 32;
        float acc[2][4][4];
#pragma unroll
        for (int i = 0; i < 2; ++i)
#pragma unroll
            for (int j = 0; j < 4; ++j)
#pragma unroll
                for (int k = 0; k < 4; ++k) acc[i][j][k] = 0.f;

        const int bk = tid >> 3, bnb = (tid & 7) * 16;
        const float* Bp = wkv1 + (size_t)bk * 256 + n0 + bnb;
        const unsigned BsW = sptr(Bs) + (bk * 136 + bnb) * 4;
#pragma unroll
        for (int i = 0; i < 4; ++i) CPA(BsW + i * 16, Bp + i * 4);
        CPC();

        for (int c = 0; c < 8; ++c) {
            const int buf = c & 1;
            CPW(0);
            __syncthreads();
            if (c < 7) {
                const float* bp = Bp + (size_t)(c + 1) * 32 * 256;
                unsigned w = BsW + (buf ^ 1) * (4352 * 4);
#pragma unroll
                for (int i = 0; i < 4; ++i) CPA(w + i * 16, bp + i * 4);
                CPC();
            }
            const float* Bb = Bs + buf * 4352;
#pragma unroll
            for (int ks = 0; ks < 4; ++ks) {
                unsigned a[2][4], bfr[4][2];
#pragma unroll
                for (int mt = 0; mt < 2; ++mt) {
                    int rr = wm + mt * 16 + (lane >> 2), cc = c * 32 + ks * 8 + (lane & 3);
                    a[mt][0] = __float_as_uint(xt[rr * 260 + cc]);
                    a[mt][1] = __float_as_uint(xt[(rr + 8) * 260 + cc]);
                    a[mt][2] = __float_as_uint(xt[rr * 260 + cc + 4]);
                    a[mt][3] = __float_as_uint(xt[(rr + 8) * 260 + cc + 4]);
                }
#pragma unroll
                for (int nt = 0; nt < 4; ++nt) {
                    int n = wn + nt * 8 + (lane >> 2), kr = ks * 8 + (lane & 3);
                    bfr[nt][0] = __float_as_uint(Bb[kr * 136 + n]);
                    bfr[nt][1] = __float_as_uint(Bb[(kr + 4) * 136 + n]);
                }
#pragma unroll
                for (int mt = 0; mt < 2; ++mt)
#pragma unroll
                    for (int nt = 0; nt < 4; ++nt) mma8(acc[mt][nt], a[mt], bfr[nt]);
            }
            __syncthreads();
        }

#pragma unroll
        for (int mt = 0; mt < 2; ++mt) {
            int rr = m0 + wm + mt * 16 + (lane >> 2);
#pragma unroll
            for (int nt = 0; nt < 4; ++nt) {
                int cc = wn + nt * 8 + (lane & 3) * 2;
                float o0 = f2tff(acc[mt][nt][0] + biass[cc]);
                float o1 = f2tff(acc[mt][nt][1] + biass[cc + 1]);
                float o2 = f2tff(acc[mt][nt][2] + biass[cc]);
                float o3 = f2tff(acc[mt][nt][3] + biass[cc + 1]);
                *(float2*)&kv1[(size_t)rr * 256 + n0 + cc] = make_float2(o0, o1);
                *(float2*)&kv1[(size_t)(rr + 8) * 256 + n0 + cc] = make_float2(o2, o3);
            }
        }
    } else if (bid < 640) {
        // ---- attn2: 4x4 window attention (128 active threads) ----
        if (tid >= 128) return;
        float* ks = smx;
        float* vs = smx + 8 * 528;
        float* ps = smx + 16 * 528;
        const int g = tid >> 4, t = tid & 15;
        const int w = ((bid - 128) << 3) + g;
        const int b = w >> 10, h = (w >> 8) & 3, win = w & 255;
        const int wy = win >> 4, wx = win & 15;
        const int n = ((wy << 2) + (t >> 2)) * 64 + (wx << 2) + (t & 3);

        const float* row = &big[((size_t)(b * 4096 + n)) * 768];
        float qr[32];
#pragma unroll
        for (int dd = 0; dd < 32; ++dd) {
            ks[(g * 16 + t) * 33 + dd] = row[256 + h * 32 + dd];
            vs[(g * 16 + t) * 33 + dd] = row[384 + h * 32 + dd];
            qr[dd] = row[128 + h * 32 + dd];
        }
        __syncwarp(0xffffffffu);

        float s[16];
        float mx = -1e30f;
#pragma unroll
        for (int m = 0; m < 16; ++m) {
            float a = 0.f;
#pragma unroll
            for (int dd = 0; dd < 32; ++dd) a += qr[dd] * ks[(g * 16 + m) * 33 + dd];
            s[m] = a * SCALE;
            mx = fmaxf(mx, s[m]);
        }
        float sum = 0.f;
#pragma unroll
        for (int m = 0; m < 16; ++m) { s[m] = __expf(s[m] - mx); sum += s[m]; }
        float inv = 1.f / sum;

        float o[32];
#pragma unroll
        for (int dd = 0; dd < 32; ++dd) o[dd] = 0.f;
#pragma unroll
        for (int m = 0; m < 16; ++m) {
            float p = s[m] * inv;
            ps[(g * 16 + t) * 17 + m] = p;
#pragma unroll
            for (int dd = 0; dd < 32; ++dd) o[dd] += p * vs[(g * 16 + m) * 33 + dd];
        }
        float* orow = &att_out[((size_t)(b * 4096 + n)) * 256 + 128 + h * 32];
#pragma unroll
        for (int dd = 0; dd < 32; ++dd) orow[dd] = o[dd];
        __syncwarp(0xffffffffu);

        float cs = 0.f;
#pragma unroll
        for (int qq = 0; qq < 16; ++qq) cs += ps[(g * 16 + qq) * 17 + t];
        atomicAdd(&lmacc[((b << 8) + win) * 16 + t], cs);
    } else {
        // ---- dwconv: lepe depthwise 3x3 ----
        int idx = (bid - 640) * 256 + tid;  // BB*NN*64
        int c4i = idx & 63;
        int n = (idx >> 6) & 4095;
        int b = idx >> 18;
        int y = n >> 6, x = n & 63;
        int c = c4i << 2;
        float4 acc = make_float4(cb[c], cb[c + 1], cb[c + 2], cb[c + 3]);
#pragma unroll
        for (int dy = 0; dy < 3; ++dy) {
            int yy = y + dy - 1;
            if ((unsigned)yy >= 64u) continue;
#pragma unroll
            for (int dx = 0; dx < 3; ++dx) {
                int xx = x + dx - 1;
                if ((unsigned)xx >= 64u) continue;
                float4 v = *(const float4*)&big[((size_t)((b << 12) + (yy << 6) + xx)) * 768 + 512 + c];
                int wi = dy * 3 + dx;
                acc.x += v.x * cw[(c + 0) * 9 + wi];
                acc.y += v.y * cw[(c + 1) * 9 + wi];
                acc.z += v.z * cw[(c + 2) * 9 + wi];
                acc.w += v.w * cw[(c + 3) * 9 + wi];
            }
        }
        *(float4*)&lepe[((size_t)((b << 12) + n)) * 256 + c] = acc;
    }
}

// ---------------- attn1: single-pass, no-max softmax, fp16 e-buffer ----------------
// smem (floats): qs 2304 | kb 2x4608 | vb 2x4608 | E(uint,1024x33) 33792 | zw 256 | zi 64 | zA 32 | zB 32
#define A1_QS 0
#define A1_KB 2304
#define A1_VB 11520
#define A1_E  20736
#define A1_ZW 54528
#define A1_ZI 54784
#define A1_ZA 54848
#define A1_ZB 54880
#define A1_SMEM_FLOATS 54912
#define A1_OP 2304  // O partials reuse kb region after last QK

__global__ __launch_bounds__(512, 1) void attn1_kernel(
    const float* __restrict__ big, const float* __restrict__ kv1,
    float* __restrict__ att_out, float* __restrict__ gacc)
{
    extern __shared__ float sm[];
    float* qs = sm + A1_QS;
    float* kb = sm + A1_KB;
    float* vb = sm + A1_VB;
    unsigned* E = (unsigned*)(sm + A1_E);
    float* zw = sm + A1_ZW;
    float* zi = sm + A1_ZI;
    float* zA = sm + A1_ZA;
    float* zB = sm + A1_ZB;
    float* op = sm + A1_OP;

    const int tid = threadIdx.x, warp = tid >> 5, lane = tid & 31;
    const int bid = blockIdx.x;
    const int bh = bid >> 6, b = bh >> 2, h = bh & 3;
    const int q0 = (bid & 63) * 64;
    const int wq = warp & 3, wk = warp >> 2;
    const int r = lane >> 2, t = lane & 3;

    // stage Q (64x32, pre-rounded tf32)
    {
        int q = tid >> 3, d4 = (tid & 7) * 4;
        *(float4*)&qs[q * 36 + d4] =
            *(const float4*)&big[(size_t)(b * 4096 + q0 + q) * 768 + h * 32 + d4];
    }
    // prefetch chunk 0 (K and V)
    const int jj = tid >> 2, db = (tid & 3) * 8;
    const size_t kbase = (size_t)(b * 1024) * 256 + h * 32;
    const size_t vbase = kbase + 128;
    const unsigned kW = sptr(kb) + (jj * 36 + db) * 4;
    const unsigned vW = sptr(vb) + (jj * 36 + db) * 4;
    {
        const float* sk = kv1 + kbase + (size_t)jj * 256 + db;
        const float* sv = kv1 + vbase + (size_t)jj * 256 + db;
        CPA(kW, sk); CPA(kW + 16, sk + 4);
        CPA(vW, sv); CPA(vW + 16, sv + 4);
        CPC();
    }
    __syncthreads();

    unsigned qa[4][4];
#pragma unroll
    for (int ks = 0; ks < 4; ++ks) {
        int rr = wq * 16 + r, cc = ks * 8 + t;
        qa[ks][0] = __float_as_uint(qs[rr * 36 + cc]);
        qa[ks][1] = __float_as_uint(qs[(rr + 8) * 36 + cc]);
        qa[ks][2] = __float_as_uint(qs[rr * 36 + cc + 4]);
        qa[ks][3] = __float_as_uint(qs[(rr + 8) * 36 + cc + 4]);
    }

    float z0 = 0.f, z1 = 0.f;
    float o4[4][4];
#pragma unroll
    for (int nt = 0; nt < 4; ++nt)
#pragma unroll
        for (int k = 0; k < 4; ++k) o4[nt][k] = 0.f;

    const int p = wq * 8 + r;   // rowpair index

    for (int ch = 0; ch < 8; ++ch) {
        CPW(0);
        __syncthreads();
        if (ch < 7) {
            const float* sk = kv1 + kbase + (size_t)((ch + 1) * 128 + jj) * 256 + db;
            const float* sv = kv1 + vbase + (size_t)((ch + 1) * 128 + jj) * 256 + db;
            unsigned kw = kW + ((ch + 1) & 1) * (4608 * 4);
            unsigned vw = vW + ((ch + 1) & 1) * (4608 * 4);
            CPA(kw, sk); CPA(kw + 16, sk + 4);
            CPA(vw, sv); CPA(vw + 16, sv + 4);
            CPC();
        }
        const float* kc = kb + (ch & 1) * 4608;
        const float* vc = vb + (ch & 1) * 4608;

        // ---- QK + exp + store e (fp16 pairs) + z ----
#pragma unroll
        for (int g = 0; g < 4; ++g) {
            float c4[4] = {0.f, 0.f, 0.f, 0.f};
            const int nb = wk * 32 + g * 8;
#pragma unroll
            for (int ks = 0; ks < 4; ++ks) {
                int n = nb + r, dr = ks * 8 + t;
                unsigned bb2[2] = { __float_as_uint(kc[n * 36 + dr]),
                                    __float_as_uint(kc[n * 36 + dr + 4]) };
                mma8(c4, qa[ks], bb2);
            }
            float e0 = __expf(fminf(c4[0] * SCALE, 11.f));
            float e1 = __expf(fminf(c4[1] * SCALE, 11.f));
            float e2 = __expf(fminf(c4[2] * SCALE, 11.f));
            float e3 = __expf(fminf(c4[3] * SCALE, 11.f));
            z0 += e0 + e1;
            z1 += e2 + e3;
            int j0 = ch * 128 + nb + 2 * t;
            __half2 h0 = __floats2half2_rn(e0, e2);
            __half2 h1 = __floats2half2_rn(e1, e3);
            E[j0 * 33 + p] = *(unsigned*)&h0;
            E[(j0 + 1) * 33 + p] = *(unsigned*)&h1;
        }
        __syncthreads();

        // ---- PV: load e in A-frag layout from E, mma with V ----
#pragma unroll
        for (int g = 0; g < 4; ++g) {
            const int nb = wk * 32 + g * 8;
            unsigned u0 = E[(ch * 128 + nb + t) * 33 + p];
            unsigned u1 = E[(ch * 128 + nb + t + 4) * 33 + p];
            float2 f0 = __half22float2(*(__half2*)&u0);
            float2 f1 = __half22float2(*(__half2*)&u1);
            unsigned af[4] = { __float_as_uint(f0.x), __float_as_uint(f0.y),
                               __float_as_uint(f1.x), __float_as_uint(f1.y) };
            int jl = nb + t;
#pragma unroll
            for (int nt = 0; nt < 4; ++nt) {
                int d = nt * 8 + r;
                unsigned bb2[2] = { __float_as_uint(vc[jl * 36 + d]),
                                    __float_as_uint(vc[(jl + 4) * 36 + d]) };
                mma8(o4[nt], af, bb2);
            }
        }
    }

    // ---- z finalize + O partial stores ----
    z0 += __shfl_xor_sync(0xffffffffu, z0, 1);
    z0 += __shfl_xor_sync(0xffffffffu, z0, 2);
    z1 += __shfl_xor_sync(0xffffffffu, z1, 1);
    z1 += __shfl_xor_sync(0xffffffffu, z1, 2);
    if (t == 0) {
        zw[wk * 64 + wq * 16 + r] = z0;
        zw[wk * 64 + wq * 16 + r + 8] = z1;
    }
    if (wk != 0) {
        float* o = op + ((wk - 1) * 4 + wq) * 544;
#pragma unroll
        for (int nt = 0; nt < 4; ++nt) {
            int col = nt * 8 + t * 2;
            *(float2*)&o[r * 34 + col] = make_float2(o4[nt][0], o4[nt][1]);
            *(float2*)&o[(r + 8) * 34 + col] = make_float2(o4[nt][2], o4[nt][3]);
        }
    }
    __syncthreads();
    if (tid < 64)
        zi[tid] = 1.f / (zw[tid] + zw[64 + tid] + zw[128 + tid] + zw[192 + tid]);
    if (tid >= 64 && tid < 96) {
        int pp = tid - 64;
        int row = ((pp >> 3) << 4) + (pp & 7);
        float sA = zw[row] + zw[64 + row] + zw[128 + row] + zw[192 + row];
        float sB = zw[row + 8] + zw[64 + row + 8] + zw[128 + row + 8] + zw[192 + row + 8];
        zA[pp] = 1.f / sA;
        zB[pp] = 1.f / sB;
    }
    __syncthreads();

    // ---- O reduce (wk==0 warps) ----
    if (wk == 0) {
        int rr = wq * 16 + r;
        float zr0 = zi[rr], zr1 = zi[rr + 8];
#pragma unroll
        for (int nt = 0; nt < 4; ++nt) {
            int col = nt * 8 + t * 2;
            float2 p0 = *(float2*)&op[(0 * 4 + wq) * 544 + r * 34 + col];
            float2 p1 = *(float2*)&op[(1 * 4 + wq) * 544 + r * 34 + col];
            float2 p2 = *(float2*)&op[(2 * 4 + wq) * 544 + r * 34 + col];
            float2 q0v = *(float2*)&op[(0 * 4 + wq) * 544 + (r + 8) * 34 + col];
            float2 q1v = *(float2*)&op[(1 * 4 + wq) * 544 + (r + 8) * 34 + col];
            float2 q2v = *(float2*)&op[(2 * 4 + wq) * 544 + (r + 8) * 34 + col];
            int gr0 = b * 4096 + q0 + rr, gr1 = gr0 + 8;
            *(float2*)&att_out[(size_t)gr0 * 256 + h * 32 + col] =
                make_float2((o4[nt][0] + p0.x + p1.x + p2.x) * zr0,
                            (o4[nt][1] + p0.y + p1.y + p2.y) * zr0);
            *(float2*)&att_out[(size_t)gr1 * 256 + h * 32 + col] =
                make_float2((o4[nt][2] + q0v.x + q1v.x + q2v.x) * zr1,
                            (o4[nt][3] + q0v.y + q1v.y + q2v.y) * zr1);
        }
    }

    // ---- gcol: column sums of normalized P from E ----
    {
        int j = tid * 2;
        float a0 = 0.f, a1 = 0.f;
#pragma unroll 8
        for (int pp = 0; pp < 32; ++pp) {
            unsigned u0 = E[j * 33 + pp];
            unsigned u1 = E[(j + 1) * 33 + pp];
            float2 f0 = __half22float2(*(__half2*)&u0);
            float2 f1 = __half22float2(*(__half2*)&u1);
            a0 += f0.x * zA[pp] + f0.y * zB[pp];
            a1 += f1.x * zA[pp] + f1.y * zB[pp];
        }
        atomicAdd(&gacc[(b << 10) + j], a0);
        atomicAdd(&gacc[(b << 10) + j + 1], a1);
    }
}

// ---------------- projmask: final projection GEMM || mask assembly ----------------
__global__ __launch_bounds__(256, 2) void projmask_kernel(
    const float* __restrict__ att, const float* __restrict__ lepe,
    const float* __restrict__ wproj, const float* __restrict__ projb,
    float* __restrict__ out,
    const float* __restrict__ gacc, const float* __restrict__ lmacc)
{
    extern __shared__ float smx[];
    if (blockIdx.x < 2) {
        gemm_core<1, 0>(att, lepe, wproj, projb, out, 256, 256, 2.f, 0,
                        blockIdx.x, blockIdx.y, smx);
    } else if (blockIdx.y < 64) {
        int idx = blockIdx.y * 256 + threadIdx.x;
        int b = idx >> 12, n = idx & 4095;
        int y = n >> 6, x = n & 63;
        float gv = gacc[(b << 10) + ((y >> 1) << 5) + (x >> 1)] * (1.f / 16384.f);
        float lv = lmacc[((b << 8) + ((y >> 2) << 4) + (x >> 2)) * 16 + ((y & 3) << 2) + (x & 3)] * (1.f / 64.f);
        float m = gv + lv;
        out[4194304 + (b << 12) + (y << 6) + x] = m;
        out[4210688 + (b << 12) + (x << 6) + y] = m;
    }
}

// ---------------- host launcher ----------------
extern "C" void kernel_launch(void* const* d_in, const int* in_sizes, int n_in,
                              void* d_out, int out_size)
{
    const float* x        = (const float*)d_in[0];
    const float* q1_w     = (const float*)d_in[1];
    const float* q1_b     = (const float*)d_in[2];
    const float* kv1_w    = (const float*)d_in[3];
    const float* kv1_b    = (const float*)d_in[4];
    const float* q2_w     = (const float*)d_in[5];
    const float* q2_b     = (const float*)d_in[6];
    const float* kv2_w    = (const float*)d_in[7];
    const float* kv2_b    = (const float*)d_in[8];
    const float* lepe_w   = (const float*)d_in[9];
    const float* lepe_b   = (const float*)d_in[10];
    const float* lepe_cw  = (const float*)d_in[11];
    const float* lepe_cb  = (const float*)d_in[12];
    const float* sr_w     = (const float*)d_in[13];
    const float* sr_b     = (const float*)d_in[14];
    const float* norm_w   = (const float*)d_in[15];
    const float* norm_b   = (const float*)d_in[16];
    const float* proj_w   = (const float*)d_in[17];
    const float* proj_b   = (const float*)d_in[18];
    float* out = (float*)d_out;

    float *p_big, *p_lepe, *p_srwt, *p_xs, *p_kv1, *p_att, *p_g, *p_lm;
    float *p_wbig, *p_bbig, *p_wkv1, *p_wproj;
    cudaGetSymbolAddress((void**)&p_big,   g_big);
    cudaGetSymbolAddress((void**)&p_lepe,  g_lepe);
    cudaGetSymbolAddress((void**)&p_srwt,  g_srwt);
    cudaGetSymbolAddress((void**)&p_xs,    g_xs);
    cudaGetSymbolAddress((void**)&p_kv1,   g_kv1);
    cudaGetSymbolAddress((void**)&p_att,   g_att);
    cudaGetSymbolAddress((void**)&p_g,     g_gacc);
    cudaGetSymbolAddress((void**)&p_lm,    g_lmacc);
    cudaGetSymbolAddress((void**)&p_wbig,  g_wbig);
    cudaGetSymbolAddress((void**)&p_bbig,  g_bbig);
    cudaGetSymbolAddress((void**)&p_wkv1,  g_wkv1);
    cudaGetSymbolAddress((void**)&p_wproj, g_wproj);

    const int gsm = (2 * 4608 + 2 * 4352 + 128) * (int)sizeof(float);  // 72192 B
    cudaFuncSetAttribute(mega1_kernel,    cudaFuncAttributeMaxDynamicSharedMemorySize, gsm);
    cudaFuncSetAttribute(projmask_kernel, cudaFuncAttributeMaxDynamicSharedMemorySize, gsm);
    const int ksm = (16640 + 8704 + 128) * (int)sizeof(float);         // 101888 B
    cudaFuncSetAttribute(mega2_kernel,    cudaFuncAttributeMaxDynamicSharedMemorySize, ksm);
    const int a1sm = A1_SMEM_FLOATS * (int)sizeof(float);              // 219648 B
    cudaFuncSetAttribute(attn1_kernel,    cudaFuncAttributeMaxDynamicSharedMemorySize, a1sm);

    // 1. fused prep
    prep_kernel<<<1024, 256>>>(q1_w, q2_w, kv2_w, lepe_w, q1_b, q2_b, kv2_b, lepe_b,
                               kv1_w, proj_w, sr_w,
                               p_wbig, p_bbig, p_wkv1, p_wproj, p_srwt, p_g, p_lm);

    // 2. big linear GEMM || sr conv GEMM
    mega1_kernel<<<dim3(8, 128), 256, gsm>>>(x, p_wbig, p_bbig, p_big, p_srwt, sr_b, p_xs);

    // 3. kv1ln GEMM || attn2 || dwconv
    mega2_kernel<<<4736, 256, ksm>>>(p_xs, p_wkv1, kv1_b, norm_w, norm_b, p_kv1,
                                     p_big, lepe_cw, lepe_cb, p_lepe, p_att, p_lm);

    // 4. attn1 (single-pass, fp16 e-buffer)
    attn1_kernel<<<1024, 512, a1sm>>>(p_big, p_kv1, p_att, p_g);

    // 5. projection GEMM || mask assembly
    projmask_kernel<<<dim3(3, 128), 256, gsm>>>(p_att, p_lepe, p_wproj, proj_b, out, p_g, p_lm);
}

// round 16
// speedup vs baseline: 1.5287x; 1.1955x over previous
#include <cuda_runtime.h>
#include <cuda_fp16.h>
#include <math.h>

// ---------------- problem constants ----------------
#define BB 4
#define NN 4096
#define N1 1024
#define SCALE 0.17677669529663687f  // 1/sqrt(32)

// ---------------- scratch ----------------
__device__ float g_big [BB*NN*768];   // cols: q1[0,128) q2[128,256) kv2[256,512) lin[512,768)
__device__ float g_lepe[BB*NN*256];
__device__ float g_srwt[1024*256];
__device__ float g_xs  [BB*N1*256];
__device__ __half g_kv1kh[BB*N1*128];      // K fp16, [b*1024+tok][128]
__device__ __half g_kv1vT[BB*4*32*N1];     // V fp16 transposed, [((b*4+h)*32+d)][tok]
__device__ float g_att [BB*NN*256];   // x1 in [0,128), x2 in [128,256)
__device__ float g_gacc[BB*N1];
__device__ float g_lmacc[BB*256*16];
__device__ float g_wbig[256*768];
__device__ float g_bbig[768];
__device__ float g_wkv1[256*256];
__device__ float g_wproj[256*256];

// ---------------- helpers ----------------
__device__ __forceinline__ unsigned f2tf(float f) {
    unsigned u;
    asm("cvt.rna.tf32.f32 %0, %1;" : "=r"(u) : "f"(f));
    return u;
}
__device__ __forceinline__ float f2tff(float f) { return __uint_as_float(f2tf(f)); }

__device__ __forceinline__ void mma8(float* d, const unsigned* a, const unsigned* b) {
    asm volatile(
        "mma.sync.aligned.m16n8k8.row.col.f32.tf32.tf32.f32 "
        "{%0,%1,%2,%3}, {%4,%5,%6,%7}, {%8,%9}, {%0,%1,%2,%3};"
        : "+f"(d[0]), "+f"(d[1]), "+f"(d[2]), "+f"(d[3])
        : "r"(a[0]), "r"(a[1]), "r"(a[2]), "r"(a[3]), "r"(b[0]), "r"(b[1]));
}

__device__ __forceinline__ void mma16h(float* d, const unsigned* a, const unsigned* b) {
    asm volatile(
        "mma.sync.aligned.m16n8k16.row.col.f32.f16.f16.f32 "
        "{%0,%1,%2,%3}, {%4,%5,%6,%7}, {%8,%9}, {%0,%1,%2,%3};"
        : "+f"(d[0]), "+f"(d[1]), "+f"(d[2]), "+f"(d[3])
        : "r"(a[0]), "r"(a[1]), "r"(a[2]), "r"(a[3]), "r"(b[0]), "r"(b[1]));
}

__device__ __forceinline__ unsigned sptr(const void* p) {
    return (unsigned)__cvta_generic_to_shared(p);
}
#define CPA(dst, src) asm volatile("cp.async.cg.shared.global [%0], [%1], 16;" :: "r"(dst), "l"(src))
#define CPC() asm volatile("cp.async.commit_group;")
#define CPW(n) asm volatile("cp.async.wait_group %0;" :: "n"(n))

// ---------------- fused prep ----------------
__global__ void prep_kernel(const float* __restrict__ q1w, const float* __restrict__ q2w,
                            const float* __restrict__ kv2w, const float* __restrict__ lepew,
                            const float* __restrict__ q1b, const float* __restrict__ q2b,
                            const float* __restrict__ kv2b, const float* __restrict__ lepeb,
                            const float* __restrict__ kv1w, const float* __restrict__ projw,
                            const float* __restrict__ srw,
                            float* __restrict__ wbig, float* __restrict__ bbig,
                            float* __restrict__ wkv1, float* __restrict__ wproj,
                            float* __restrict__ srwt,
                            float* __restrict__ gacc, float* __restrict__ lmacc)
{
    int idx = blockIdx.x * blockDim.x + threadIdx.x;   // 262144
    {
        int o = idx & 255, f = idx >> 8, c = f & 255, q = f >> 8;
        srwt[idx] = f2tff(srw[(o << 10) + (c << 2) + q]);
    }
    if (idx < 196608) {
        int j = idx % 768, k = idx / 768;
        float v;
        if (j < 128)      v = q1w[k * 128 + j];
        else if (j < 256) v = q2w[k * 128 + j - 128];
        else if (j < 512) v = kv2w[k * 256 + j - 256];
        else              v = lepew[k * 256 + j - 512];
        wbig[idx] = f2tff(v);
        if (k == 0) {
            float bv;
            if (j < 128)      bv = q1b[j];
            else if (j < 256) bv = q2b[j - 128];
            else if (j < 512) bv = kv2b[j - 256];
            else              bv = lepeb[j - 512];
            bbig[j] = bv;
        }
    }
    if (idx < 65536) {
        wkv1[idx]  = f2tff(kv1w[idx]);
        wproj[idx] = f2tff(projw[idx]);
    }
    if (idx < 16384) lmacc[idx] = 0.f;
    if (idx < 4096)  gacc[idx]  = 0.f;
}

// ---------------- pipelined tf32 GEMM core ----------------
template<int FUSE, int XCOL>
__device__ __forceinline__ void gemm_core(
    const float* __restrict__ A, const float* __restrict__ A2,
    const float* __restrict__ Bw, const float* __restrict__ bias,
    float* __restrict__ C, int K, int Nn, float oscale, int oround,
    int bx, int by, float* smx)
{
    float* As = smx;                   // [2][128*36]
    float* Bs = smx + 2 * 4608;        // [2][32*136]
    float* biass = smx + 2 * 4608 + 2 * 4352;
    const int tid = threadIdx.x, warp = tid >> 5, lane = tid & 31;
    const int m0 = by * 128, n0 = bx * 128;
    const int wm = (warp & 1) * 64, wn = (warp >> 1) * 32;
    if (tid < 128) biass[tid] = bias[n0 + tid];

    float acc[4][4][4];
#pragma unroll
    for (int i = 0; i < 4; ++i)
#pragma unroll
        for (int j = 0; j < 4; ++j)
#pragma unroll
            for (int k = 0; k < 4; ++k) acc[i][j][k] = 0.f;

    const int am = tid >> 1, akb = (tid & 1) * 16;
    const int bk = tid >> 3, bnb = (tid & 7) * 16;
    const int row = m0 + am;
    const int xb = row >> 10, xm = row & 1023;
    const int ii2 = (xm >> 5) << 1, jj2 = (xm & 31) << 1;
    const int basepix = xb << 12;

    const float* Ap  = A + (size_t)row * K + akb;
    const float* A2p = FUSE ? (A2 + (size_t)row * K + akb) : (const float*)0;
    const float* Bp  = Bw + (size_t)bk * Nn + n0 + bnb;
    const unsigned BsW = sptr(Bs) + (bk * 136 + bnb) * 4;

    float4 ar[4], ar2[4];
#pragma unroll
    for (int i = 0; i < 4; ++i) {
        if (XCOL) {
            int k = akb + i * 4, f = k >> 8, cc = k & 255;
            int n = ((ii2 + (f >> 1)) << 6) + jj2 + (f & 1);
            ar[i] = *(const float4*)&A[(size_t)(basepix + n) * 256 + cc];
        } else {
            ar[i] = *(const float4*)(Ap + i * 4);
        }
    }
    if (FUSE) {
#pragma unroll
        for (int i = 0; i < 4; ++i) ar2[i] = *(const float4*)(A2p + i * 4);
    }
#pragma unroll
    for (int i = 0; i < 4; ++i) CPA(BsW + i * 16, Bp + i * 4);
    CPC();

    const int nc = K >> 5;
    for (int c = 0; c < nc; ++c) {
        const int buf = c & 1;
        CPW(0);
        {
            float* dst = As + buf * 4608 + am * 36 + akb;
#pragma unroll
            for (int i = 0; i < 4; ++i) {
                float4 v = ar[i];
                if (FUSE) { float4 w = ar2[i]; v.x += w.x; v.y += w.y; v.z += w.z; v.w += w.w; }
                dst[i * 4 + 0] = f2tff(v.x); dst[i * 4 + 1] = f2tff(v.y);
                dst[i * 4 + 2] = f2tff(v.z); dst[i * 4 + 3] = f2tff(v.w);
            }
        }
        __syncthreads();
        if (c + 1 < nc) {
            const float* bp = Bp + (size_t)(c + 1) * 32 * Nn;
            unsigned w = BsW + (buf ^ 1) * (4352 * 4);
#pragma unroll
            for (int i = 0; i < 4; ++i) CPA(w + i * 16, bp + i * 4);
            CPC();
#pragma unroll
            for (int i = 0; i < 4; ++i) {
                if (XCOL) {
                    int k = (c + 1) * 32 + akb + i * 4, f = k >> 8, cc = k & 255;
                    int n = ((ii2 + (f >> 1)) << 6) + jj2 + (f & 1);
                    ar[i] = *(const float4*)&A[(size_t)(basepix + n) * 256 + cc];
                } else {
                    ar[i] = *(const float4*)(Ap + (c + 1) * 32 + i * 4);
                }
            }
            if (FUSE) {
                const float* a2p = A2p + (c + 1) * 32;
#pragma unroll
                for (int i = 0; i < 4; ++i) ar2[i] = *(const float4*)(a2p + i * 4);
            }
        }
        const float* Ab = As + buf * 4608;
        const float* Bb = Bs + buf * 4352;
#pragma unroll
        for (int ks = 0; ks < 4; ++ks) {
            unsigned a[4][4], bfr[4][2];
#pragma unroll
            for (int mt = 0; mt < 4; ++mt) {
                int r = wm + mt * 16 + (lane >> 2), cc = ks * 8 + (lane & 3);
                a[mt][0] = __float_as_uint(Ab[r * 36 + cc]);
                a[mt][1] = __float_as_uint(Ab[(r + 8) * 36 + cc]);
                a[mt][2] = __float_as_uint(Ab[r * 36 + cc + 4]);
                a[mt][3] = __float_as_uint(Ab[(r + 8) * 36 + cc + 4]);
            }
#pragma unroll
            for (int nt = 0; nt < 4; ++nt) {
                int n = wn + nt * 8 + (lane >> 2), kr = ks * 8 + (lane & 3);
                bfr[nt][0] = __float_as_uint(Bb[kr * 136 + n]);
                bfr[nt][1] = __float_as_uint(Bb[(kr + 4) * 136 + n]);
            }
#pragma unroll
            for (int mt = 0; mt < 4; ++mt)
#pragma unroll
                for (int nt = 0; nt < 4; ++nt) mma8(acc[mt][nt], a[mt], bfr[nt]);
        }
    }

#pragma unroll
    for (int mt = 0; mt < 4; ++mt) {
        int r = m0 + wm + mt * 16 + (lane >> 2);
#pragma unroll
        for (int nt = 0; nt < 4; ++nt) {
            int cc = wn + nt * 8 + (lane & 3) * 2;
            float o0 = (acc[mt][nt][0] + biass[cc]) * oscale;
            float o1 = (acc[mt][nt][1] + biass[cc + 1]) * oscale;
            float o2 = (acc[mt][nt][2] + biass[cc]) * oscale;
            float o3 = (acc[mt][nt][3] + biass[cc + 1]) * oscale;
            if (oround) { o0 = f2tff(o0); o1 = f2tff(o1); o2 = f2tff(o2); o3 = f2tff(o3); }
            *(float2*)&C[(size_t)r * Nn + n0 + cc] = make_float2(o0, o1);
            *(float2*)&C[(size_t)(r + 8) * Nn + n0 + cc] = make_float2(o2, o3);
        }
    }
}

// ---------------- mega1: big linear GEMM || sr conv GEMM (im2col fused) ----------------
__global__ __launch_bounds__(256, 2) void mega1_kernel(
    const float* __restrict__ x,
    const float* __restrict__ wbig, const float* __restrict__ bbig, float* __restrict__ big,
    const float* __restrict__ srwt, const float* __restrict__ srb, float* __restrict__ xs)
{
    extern __shared__ float smx[];
    if (blockIdx.x < 6) {
        gemm_core<0, 0>(x, nullptr, wbig, bbig, big, 256, 768, 1.f, 1,
                        blockIdx.x, blockIdx.y, smx);
    } else if (blockIdx.y < 32) {
        gemm_core<0, 1>(x, nullptr, srwt, srb, xs, 1024, 256, 1.f, 0,
                        blockIdx.x - 6, blockIdx.y, smx);
    }
}

// ---------------- mega2: kv1ln GEMM (fp16 K/V^T out) || attn2 || dwconv ----------------
// grid: [0,128) kv1ln, [128,640) attn2, [640,4736) dwconv
__global__ __launch_bounds__(256, 2) void mega2_kernel(
    const float* __restrict__ xs, const float* __restrict__ wkv1,
    const float* __restrict__ kv1b, const float* __restrict__ normw,
    const float* __restrict__ normb, __half* __restrict__ kv1kh,
    __half* __restrict__ kv1vT,
    const float* __restrict__ big, const float* __restrict__ cw,
    const float* __restrict__ cb, float* __restrict__ lepe,
    float* __restrict__ att_out, float* __restrict__ lmacc)
{
    extern __shared__ float smx[];
    const int bid = blockIdx.x;
    const int tid = threadIdx.x;

    if (bid < 128) {
        // ---- kv1ln: LN+GELU fused into kv1 GEMM, fp16 outputs ----
        float* xt = smx;                       // 16640
        float* Bs = smx + 16640;               // 8704
        float* biass = smx + 16640 + 8704;     // 128
        const int warp = tid >> 5, lane = tid & 31;
        const int m0 = (bid >> 1) * 64, n0 = (bid & 1) * 128;
        if (tid < 128) biass[tid] = kv1b[n0 + tid];

        const int r = tid >> 2, cq = (tid & 3) * 64;
        {
            const float* src = xs + (size_t)(m0 + r) * 256 + cq;
#pragma unroll
            for (int i = 0; i < 16; ++i)
                *(float4*)&xt[r * 260 + cq + i * 4] = *(const float4*)(src + i * 4);
        }
        __syncthreads();

        {
            float s = 0.f, s2 = 0.f;
#pragma unroll
            for (int i = 0; i < 64; ++i) { float v = xt[r * 260 + cq + i]; s += v; s2 += v * v; }
            s  += __shfl_xor_sync(0xffffffffu, s, 1);  s  += __shfl_xor_sync(0xffffffffu, s, 2);
            s2 += __shfl_xor_sync(0xffffffffu, s2, 1); s2 += __shfl_xor_sync(0xffffffffu, s2, 2);
            float mean = s * (1.f / 256.f);
            float var = s2 * (1.f / 256.f) - mean * mean;
            float inv = rsqrtf(var + 1e-5f);
#pragma unroll 8
            for (int i = 0; i < 64; ++i) {
                int c = cq + i;
                float y = (xt[r * 260 + c] - mean) * inv * normw[c] + normb[c];
                xt[r * 260 + c] = f2tff(0.5f * y * (1.0f + erff(y * 0.70710678118654752f)));
            }
        }
        __syncthreads();

        const int wm = (warp & 1) * 32, wn = (warp >> 1) * 32;
        float acc[2][4][4];
#pragma unroll
        for (int i = 0; i < 2; ++i)
#pragma unroll
            for (int j = 0; j < 4; ++j)
#pragma unroll
                for (int k = 0; k < 4; ++k) acc[i][j][k] = 0.f;

        const int bk = tid >> 3, bnb = (tid & 7) * 16;
        const float* Bp = wkv1 + (size_t)bk * 256 + n0 + bnb;
        const unsigned BsW = sptr(Bs) + (bk * 136 + bnb) * 4;
#pragma unroll
        for (int i = 0; i < 4; ++i) CPA(BsW + i * 16, Bp + i * 4);
        CPC();

        for (int c = 0; c < 8; ++c) {
            const int buf = c & 1;
            CPW(0);
            __syncthreads();
            if (c < 7) {
                const float* bp = Bp + (size_t)(c + 1) * 32 * 256;
                unsigned w = BsW + (buf ^ 1) * (4352 * 4);
#pragma unroll
                for (int i = 0; i < 4; ++i) CPA(w + i * 16, bp + i * 4);
                CPC();
            }
            const float* Bb = Bs + buf * 4352;
#pragma unroll
            for (int ks = 0; ks < 4; ++ks) {
                unsigned a[2][4], bfr[4][2];
#pragma unroll
                for (int mt = 0; mt < 2; ++mt) {
                    int rr = wm + mt * 16 + (lane >> 2), cc = c * 32 + ks * 8 + (lane & 3);
                    a[mt][0] = __float_as_uint(xt[rr * 260 + cc]);
                    a[mt][1] = __float_as_uint(xt[(rr + 8) * 260 + cc]);
                    a[mt][2] = __float_as_uint(xt[rr * 260 + cc + 4]);
                    a[mt][3] = __float_as_uint(xt[(rr + 8) * 260 + cc + 4]);
                }
#pragma unroll
                for (int nt = 0; nt < 4; ++nt) {
                    int n = wn + nt * 8 + (lane >> 2), kr = ks * 8 + (lane & 3);
                    bfr[nt][0] = __float_as_uint(Bb[kr * 136 + n]);
                    bfr[nt][1] = __float_as_uint(Bb[(kr + 4) * 136 + n]);
                }
#pragma unroll
                for (int mt = 0; mt < 2; ++mt)
#pragma unroll
                    for (int nt = 0; nt < 4; ++nt) mma8(acc[mt][nt], a[mt], bfr[nt]);
            }
            __syncthreads();
        }

#pragma unroll
        for (int mt = 0; mt < 2; ++mt) {
            int rr = m0 + wm + mt * 16 + (lane >> 2);
#pragma unroll
            for (int nt = 0; nt < 4; ++nt) {
                int cc = wn + nt * 8 + (lane & 3) * 2;
                float o0 = acc[mt][nt][0] + biass[cc];
                float o1 = acc[mt][nt][1] + biass[cc + 1];
                float o2 = acc[mt][nt][2] + biass[cc];
                float o3 = acc[mt][nt][3] + biass[cc + 1];
                if (n0 == 0) {
                    // K half: fp16 key-major
                    *(__half2*)&kv1kh[(size_t)rr * 128 + cc] = __floats2half2_rn(o0, o1);
                    *(__half2*)&kv1kh[(size_t)(rr + 8) * 128 + cc] = __floats2half2_rn(o2, o3);
                } else {
                    // V half: fp16 transposed [((b*4+h)*32+d)][tok]
                    int hh = cc >> 5, dd = cc & 31;
                    int b_ = rr >> 10, tok = rr & 1023;
                    size_t base = ((size_t)(b_ * 4 + hh) * 32 + dd) * 1024;
                    kv1vT[base + tok]        = __float2half_rn(o0);
                    kv1vT[base + 1024 + tok] = __float2half_rn(o1);
                    kv1vT[base + tok + 8]        = __float2half_rn(o2);
                    kv1vT[base + 1024 + tok + 8] = __float2half_rn(o3);
                }
            }
        }
    } else if (bid < 640) {
        // ---- attn2: 4x4 window attention (128 active threads) ----
        if (tid >= 128) return;
        float* ks = smx;
        float* vs = smx + 8 * 528;
        float* ps = smx + 16 * 528;
        const int g = tid >> 4, t = tid & 15;
        const int w = ((bid - 128) << 3) + g;
        const int b = w >> 10, h = (w >> 8) & 3, win = w & 255;
        const int wy = win >> 4, wx = win & 15;
        const int n = ((wy << 2) + (t >> 2)) * 64 + (wx << 2) + (t & 3);

        const float* row = &big[((size_t)(b * 4096 + n)) * 768];
        float qr[32];
#pragma unroll
        for (int dd = 0; dd < 32; ++dd) {
            ks[(g * 16 + t) * 33 + dd] = row[256 + h * 32 + dd];
            vs[(g * 16 + t) * 33 + dd] = row[384 + h * 32 + dd];
            qr[dd] = row[128 + h * 32 + dd];
        }
        __syncwarp(0xffffffffu);

        float s[16];
        float mx = -1e30f;
#pragma unroll
        for (int m = 0; m < 16; ++m) {
            float a = 0.f;
#pragma unroll
            for (int dd = 0; dd < 32; ++dd) a += qr[dd] * ks[(g * 16 + m) * 33 + dd];
            s[m] = a * SCALE;
            mx = fmaxf(mx, s[m]);
        }
        float sum = 0.f;
#pragma unroll
        for (int m = 0; m < 16; ++m) { s[m] = __expf(s[m] - mx); sum += s[m]; }
        float inv = 1.f / sum;

        float o[32];
#pragma unroll
        for (int dd = 0; dd < 32; ++dd) o[dd] = 0.f;
#pragma unroll
        for (int m = 0; m < 16; ++m) {
            float p = s[m] * inv;
            ps[(g * 16 + t) * 17 + m] = p;
#pragma unroll
            for (int dd = 0; dd < 32; ++dd) o[dd] += p * vs[(g * 16 + m) * 33 + dd];
        }
        float* orow = &att_out[((size_t)(b * 4096 + n)) * 256 + 128 + h * 32];
#pragma unroll
        for (int dd = 0; dd < 32; ++dd) orow[dd] = o[dd];
        __syncwarp(0xffffffffu);

        float cs = 0.f;
#pragma unroll
        for (int qq = 0; qq < 16; ++qq) cs += ps[(g * 16 + qq) * 17 + t];
        atomicAdd(&lmacc[((b << 8) + win) * 16 + t], cs);
    } else {
        // ---- dwconv: lepe depthwise 3x3 ----
        int idx = (bid - 640) * 256 + tid;  // BB*NN*64
        int c4i = idx & 63;
        int n = (idx >> 6) & 4095;
        int b = idx >> 18;
        int y = n >> 6, x = n & 63;
        int c = c4i << 2;
        float4 acc = make_float4(cb[c], cb[c + 1], cb[c + 2], cb[c + 3]);
#pragma unroll
        for (int dy = 0; dy < 3; ++dy) {
            int yy = y + dy - 1;
            if ((unsigned)yy >= 64u) continue;
#pragma unroll
            for (int dx = 0; dx < 3; ++dx) {
                int xx = x + dx - 1;
                if ((unsigned)xx >= 64u) continue;
                float4 v = *(const float4*)&big[((size_t)((b << 12) + (yy << 6) + xx)) * 768 + 512 + c];
                int wi = dy * 3 + dx;
                acc.x += v.x * cw[(c + 0) * 9 + wi];
                acc.y += v.y * cw[(c + 1) * 9 + wi];
                acc.z += v.z * cw[(c + 2) * 9 + wi];
                acc.w += v.w * cw[(c + 3) * 9 + wi];
            }
        }
        *(float4*)&lepe[((size_t)((b << 12) + n)) * 256 + c] = acc;
    }
}

// ---------------- attn1: single-pass fp16 mma, reg-resident P ----------------
// smem (4B units): qh 1152 | kh 2x2560 | vT 2x2176 | E 33792 | zw 256 | zi 64 | zA 32 | zB 32
#define A1_QH 0
#define A1_KH 1152
#define A1_VT 6272
#define A1_E  10624
#define A1_ZW 44416
#define A1_ZI 44672
#define A1_ZA 44736
#define A1_ZB 44768
#define A1_SMEM_U 44800
#define A1_OP 1152  // O partials overlay kh/vT after final chunk

__global__ __launch_bounds__(512, 1) void attn1_kernel(
    const float* __restrict__ big, const __half* __restrict__ kv1kh,
    const __half* __restrict__ kv1vT,
    float* __restrict__ att_out, float* __restrict__ gacc)
{
    extern __shared__ float sm[];
    unsigned* qh = (unsigned*)(sm + A1_QH);
    unsigned* kh = (unsigned*)(sm + A1_KH);
    unsigned* vT = (unsigned*)(sm + A1_VT);
    unsigned* E  = (unsigned*)(sm + A1_E);
    float* zw = sm + A1_ZW;
    float* zi = sm + A1_ZI;
    float* zA = sm + A1_ZA;
    float* zB = sm + A1_ZB;
    float* op = sm + A1_OP;

    const int tid = threadIdx.x, warp = tid >> 5, lane = tid & 31;
    const int bid = blockIdx.x;
    const int bh = bid >> 6, b = bh >> 2, h = bh & 3;
    const int q0 = (bid & 63) * 64;
    const int wq = warp & 3, wk = warp >> 2;
    const int g = lane >> 2, t = lane & 3;
    const int R = wq * 16 + g;
    const int p = wq * 8 + g;

    // stage Q (64x32 fp32 -> fp16 pairs)
#pragma unroll
    for (int i = 0; i < 2; ++i) {
        int idx = tid * 2 + i;
        int q = idx >> 4, pp = idx & 15;
        float2 v = *(const float2*)&big[(size_t)(b * 4096 + q0 + q) * 768 + h * 32 + pp * 2];
        __half2 hv = __floats2half2_rn(v.x, v.y);
        qh[q * 18 + pp] = *(unsigned*)&hv;
    }
    // prefetch chunk 0 (K key-major fp16, V transposed fp16)
    const int kkey = tid >> 2, kseg = tid & 3;
    const int vd = tid >> 4, vseg = tid & 15;
    const __half* Kbase = kv1kh + (size_t)(b * 1024) * 128 + h * 32;
    const __half* Vbase = kv1vT + (size_t)((b * 4 + h) * 32) * 1024;
    const unsigned kW = sptr(kh) + (kkey * 20 + kseg * 4) * 4;
    const unsigned vW = sptr(vT) + (vd * 68 + vseg * 4) * 4;
    CPA(kW, Kbase + (size_t)kkey * 128 + kseg * 8);
    CPA(vW, Vbase + (size_t)vd * 1024 + vseg * 8);
    CPC();
    __syncthreads();

    unsigned qa0[4] = { qh[R * 18 + t],     qh[(R + 8) * 18 + t],
                        qh[R * 18 + t + 4], qh[(R + 8) * 18 + t + 4] };
    unsigned qa1[4] = { qh[R * 18 + 8 + t],  qh[(R + 8) * 18 + 8 + t],
                        qh[R * 18 + 12 + t], qh[(R + 8) * 18 + 12 + t] };

    float z0 = 0.f, z1 = 0.f;
    float o4[4][4];
#pragma unroll
    for (int nt = 0; nt < 4; ++nt)
#pragma unroll
        for (int k = 0; k < 4; ++k) o4[nt][k] = 0.f;

    for (int ch = 0; ch < 8; ++ch) {
        CPW(0);
        __syncthreads();
        if (ch < 7) {
            CPA(kW + ((ch + 1) & 1) * (2560 * 4),
                Kbase + (size_t)((ch + 1) * 128 + kkey) * 128 + kseg * 8);
            CPA(vW + ((ch + 1) & 1) * (2176 * 4),
                Vbase + (size_t)vd * 1024 + (ch + 1) * 128 + vseg * 8);
            CPC();
        }
        const unsigned* kc = kh + (ch & 1) * 2560;
        const unsigned* vc = vT + (ch & 1) * 2176;

#pragma unroll
        for (int g2 = 0; g2 < 2; ++g2) {
            const int kb16 = wk * 32 + g2 * 16;
            // QK: two adjacent 8-key tiles
            float ca[4] = {0.f, 0.f, 0.f, 0.f};
            float cbv[4] = {0.f, 0.f, 0.f, 0.f};
            {
                const unsigned* kr = kc + (kb16 + g) * 20;
                unsigned b0[2] = { kr[t], kr[t + 4] };
                unsigned b1[2] = { kr[8 + t], kr[12 + t] };
                mma16h(ca, qa0, b0);
                mma16h(ca, qa1, b1);
                const unsigned* kr2 = kc + (kb16 + 8 + g) * 20;
                unsigned b0b[2] = { kr2[t], kr2[t + 4] };
                unsigned b1b[2] = { kr2[8 + t], kr2[12 + t] };
                mma16h(cbv, qa0, b0b);
                mma16h(cbv, qa1, b1b);
            }
            float eA0 = __expf(fminf(ca[0] * SCALE, 11.f));
            float eA1 = __expf(fminf(ca[1] * SCALE, 11.f));
            float eA2 = __expf(fminf(ca[2] * SCALE, 11.f));
            float eA3 = __expf(fminf(ca[3] * SCALE, 11.f));
            float eB0 = __expf(fminf(cbv[0] * SCALE, 11.f));
            float eB1 = __expf(fminf(cbv[1] * SCALE, 11.f));
            float eB2 = __expf(fminf(cbv[2] * SCALE, 11.f));
            float eB3 = __expf(fminf(cbv[3] * SCALE, 11.f));
            z0 += eA0 + eA1 + eB0 + eB1;
            z1 += eA2 + eA3 + eB2 + eB3;
            // E store for gcol (column-major half2 of rows (R, R+8))
            int j0 = ch * 128 + kb16 + 2 * t;
            __half2 h0 = __floats2half2_rn(eA0, eA2);
            __half2 h1 = __floats2half2_rn(eA1, eA3);
            __half2 h2v = __floats2half2_rn(eB0, eB2);
            __half2 h3v = __floats2half2_rn(eB1, eB3);
            E[j0 * 33 + p] = *(unsigned*)&h0;
            E[(j0 + 1) * 33 + p] = *(unsigned*)&h1;
            E[(j0 + 8) * 33 + p] = *(unsigned*)&h2v;
            E[(j0 + 9) * 33 + p] = *(unsigned*)&h3v;
            // PV A-frag directly from QK C-frags (no permute needed for fp16 k16)
            __half2 af0 = __floats2half2_rn(eA0, eA1);
            __half2 af1 = __floats2half2_rn(eA2, eA3);
            __half2 af2 = __floats2half2_rn(eB0, eB1);
            __half2 af3 = __floats2half2_rn(eB2, eB3);
            unsigned af[4] = { *(unsigned*)&af0, *(unsigned*)&af1,
                               *(unsigned*)&af2, *(unsigned*)&af3 };
            const int pb = kb16 >> 1;
#pragma unroll
            for (int nt = 0; nt < 4; ++nt) {
                const unsigned* vr = vc + (nt * 8 + g) * 68 + pb;
                unsigned bv[2] = { vr[t], vr[4 + t] };
                mma16h(o4[nt], af, bv);
            }
        }
    }
    __syncthreads();   // all smem reads done; op may overlay kh/vT

    // ---- z finalize + O partial stores ----
    z0 += __shfl_xor_sync(0xffffffffu, z0, 1);
    z0 += __shfl_xor_sync(0xffffffffu, z0, 2);
    z1 += __shfl_xor_sync(0xffffffffu, z1, 1);
    z1 += __shfl_xor_sync(0xffffffffu, z1, 2);
    if (t == 0) {
        zw[wk * 64 + wq * 16 + g] = z0;
        zw[wk * 64 + wq * 16 + g + 8] = z1;
    }
    if (wk != 0) {
        float* o = op + ((wk - 1) * 4 + wq) * 544;
#pragma unroll
        for (int nt = 0; nt < 4; ++nt) {
            int col = nt * 8 + t * 2;
            *(float2*)&o[g * 34 + col] = make_float2(o4[nt][0], o4[nt][1]);
            *(float2*)&o[(g + 8) * 34 + col] = make_float2(o4[nt][2], o4[nt][3]);
        }
    }
    __syncthreads();
    if (tid < 64)
        zi[tid] = 1.f / (zw[tid] + zw[64 + tid] + zw[128 + tid] + zw[192 + tid]);
    if (tid >= 64 && tid < 96) {
        int pp = tid - 64;
        int row = ((pp >> 3) << 4) + (pp & 7);
        float sA = zw[row] + zw[64 + row] + zw[128 + row] + zw[192 + row];
        float sB = zw[row + 8] + zw[64 + row + 8] + zw[128 + row + 8] + zw[192 + row + 8];
        zA[pp] = 1.f / sA;
        zB[pp] = 1.f / sB;
    }
    __syncthreads();

    // ---- O reduce (wk==0 warps) ----
    if (wk == 0) {
        int rr = wq * 16 + g;
        float zr0 = zi[rr], zr1 = zi[rr + 8];
#pragma unroll
        for (int nt = 0; nt < 4; ++nt) {
            int col = nt * 8 + t * 2;
            float2 p0 = *(float2*)&op[(0 * 4 + wq) * 544 + g * 34 + col];
            float2 p1 = *(float2*)&op[(1 * 4 + wq) * 544 + g * 34 + col];
            float2 p2 = *(float2*)&op[(2 * 4 + wq) * 544 + g * 34 + col];
            float2 q0v = *(float2*)&op[(0 * 4 + wq) * 544 + (g + 8) * 34 + col];
            float2 q1v = *(float2*)&op[(1 * 4 + wq) * 544 + (g + 8) * 34 + col];
            float2 q2v = *(float2*)&op[(2 * 4 + wq) * 544 + (g + 8) * 34 + col];
            int gr0 = b * 4096 + q0 + rr, gr1 = gr0 + 8;
            *(float2*)&att_out[(size_t)gr0 * 256 + h * 32 + col] =
                make_float2((o4[nt][0] + p0.x + p1.x + p2.x) * zr0,
                            (o4[nt][1] + p0.y + p1.y + p2.y) * zr0);
            *(float2*)&att_out[(size_t)gr1 * 256 + h * 32 + col] =
                make_float2((o4[nt][2] + q0v.x + q1v.x + q2v.x) * zr1,
                            (o4[nt][3] + q0v.y + q1v.y + q2v.y) * zr1);
        }
    }

    // ---- gcol: column sums of normalized P from E ----
    {
        int j = tid * 2;
        float a0 = 0.f, a1 = 0.f;
#pragma unroll 8
        for (int pp = 0; pp < 32; ++pp) {
            unsigned u0 = E[j * 33 + pp];
            unsigned u1 = E[(j + 1) * 33 + pp];
            float2 f0 = __half22float2(*(__half2*)&u0);
            float2 f1 = __half22float2(*(__half2*)&u1);
            a0 += f0.x * zA[pp] + f0.y * zB[pp];
            a1 += f1.x * zA[pp] + f1.y * zB[pp];
        }
        atomicAdd(&gacc[(b << 10) + j], a0);
        atomicAdd(&gacc[(b << 10) + j + 1], a1);
    }
}

// ---------------- projmask: final projection GEMM || mask assembly ----------------
__global__ __launch_bounds__(256, 2) void projmask_kernel(
    const float* __restrict__ att, const float* __restrict__ lepe,
    const float* __restrict__ wproj, const float* __restrict__ projb,
    float* __restrict__ out,
    const float* __restrict__ gacc, const float* __restrict__ lmacc)
{
    extern __shared__ float smx[];
    if (blockIdx.x < 2) {
        gemm_core<1, 0>(att, lepe, wproj, projb, out, 256, 256, 2.f, 0,
                        blockIdx.x, blockIdx.y, smx);
    } else if (blockIdx.y < 64) {
        int idx = blockIdx.y * 256 + threadIdx.x;
        int b = idx >> 12, n = idx & 4095;
        int y = n >> 6, x = n & 63;
        float gv = gacc[(b << 10) + ((y >> 1) << 5) + (x >> 1)] * (1.f / 16384.f);
        float lv = lmacc[((b << 8) + ((y >> 2) << 4) + (x >> 2)) * 16 + ((y & 3) << 2) + (x & 3)] * (1.f / 64.f);
        float m = gv + lv;
        out[4194304 + (b << 12) + (y << 6) + x] = m;
        out[4210688 + (b << 12) + (x << 6) + y] = m;
    }
}

// ---------------- host launcher ----------------
extern "C" void kernel_launch(void* const* d_in, const int* in_sizes, int n_in,
                              void* d_out, int out_size)
{
    const float* x        = (const float*)d_in[0];
    const float* q1_w     = (const float*)d_in[1];
    const float* q1_b     = (const float*)d_in[2];
    const float* kv1_w    = (const float*)d_in[3];
    const float* kv1_b    = (const float*)d_in[4];
    const float* q2_w     = (const float*)d_in[5];
    const float* q2_b     = (const float*)d_in[6];
    const float* kv2_w    = (const float*)d_in[7];
    const float* kv2_b    = (const float*)d_in[8];
    const float* lepe_w   = (const float*)d_in[9];
    const float* lepe_b   = (const float*)d_in[10];
    const float* lepe_cw  = (const float*)d_in[11];
    const float* lepe_cb  = (const float*)d_in[12];
    const float* sr_w     = (const float*)d_in[13];
    const float* sr_b     = (const float*)d_in[14];
    const float* norm_w   = (const float*)d_in[15];
    const float* norm_b   = (const float*)d_in[16];
    const float* proj_w   = (const float*)d_in[17];
    const float* proj_b   = (const float*)d_in[18];
    float* out = (float*)d_out;

    float *p_big, *p_lepe, *p_srwt, *p_xs, *p_att, *p_g, *p_lm;
    float *p_wbig, *p_bbig, *p_wkv1, *p_wproj;
    __half *p_kh, *p_vT;
    cudaGetSymbolAddress((void**)&p_big,   g_big);
    cudaGetSymbolAddress((void**)&p_lepe,  g_lepe);
    cudaGetSymbolAddress((void**)&p_srwt,  g_srwt);
    cudaGetSymbolAddress((void**)&p_xs,    g_xs);
    cudaGetSymbolAddress((void**)&p_kh,    g_kv1kh);
    cudaGetSymbolAddress((void**)&p_vT,    g_kv1vT);
    cudaGetSymbolAddress((void**)&p_att,   g_att);
    cudaGetSymbolAddress((void**)&p_g,     g_gacc);
    cudaGetSymbolAddress((void**)&p_lm,    g_lmacc);
    cudaGetSymbolAddress((void**)&p_wbig,  g_wbig);
    cudaGetSymbolAddress((void**)&p_bbig,  g_bbig);
    cudaGetSymbolAddress((void**)&p_wkv1,  g_wkv1);
    cudaGetSymbolAddress((void**)&p_wproj, g_wproj);

    const int gsm = (2 * 4608 + 2 * 4352 + 128) * (int)sizeof(float);  // 72192 B
    cudaFuncSetAttribute(mega1_kernel,    cudaFuncAttributeMaxDynamicSharedMemorySize, gsm);
    cudaFuncSetAttribute(projmask_kernel, cudaFuncAttributeMaxDynamicSharedMemorySize, gsm);
    const int ksm = (16640 + 8704 + 128) * (int)sizeof(float);         // 101888 B
    cudaFuncSetAttribute(mega2_kernel,    cudaFuncAttributeMaxDynamicSharedMemorySize, ksm);
    const int a1sm = A1_SMEM_U * 4;                                    // 179200 B
    cudaFuncSetAttribute(attn1_kernel,    cudaFuncAttributeMaxDynamicSharedMemorySize, a1sm);

    // 1. fused prep
    prep_kernel<<<1024, 256>>>(q1_w, q2_w, kv2_w, lepe_w, q1_b, q2_b, kv2_b, lepe_b,
                               kv1_w, proj_w, sr_w,
                               p_wbig, p_bbig, p_wkv1, p_wproj, p_srwt, p_g, p_lm);

    // 2. big linear GEMM || sr conv GEMM
    mega1_kernel<<<dim3(8, 128), 256, gsm>>>(x, p_wbig, p_bbig, p_big, p_srwt, sr_b, p_xs);

    // 3. kv1ln GEMM (fp16 K/V^T) || attn2 || dwconv
    mega2_kernel<<<4736, 256, ksm>>>(p_xs, p_wkv1, kv1_b, norm_w, norm_b, p_kh, p_vT,
                                     p_big, lepe_cw, lepe_cb, p_lepe, p_att, p_lm);

    // 4. attn1 (fp16 mma, reg-resident P)
    attn1_kernel<<<1024, 512, a1sm>>>(p_big, p_kh, p_vT, p_att, p_g);

    // 5. projection GEMM || mask assembly
    projmask_kernel<<<dim3(3, 128), 256, gsm>>>(p_att, p_lepe, p_wproj, proj_b, out, p_g, p_lm);
}